// round 13
// baseline (speedup 1.0000x reference)
#include <cuda_runtime.h>
#include <math.h>
#include <stdint.h>

#define NLAYER 4
#define BB 2
#define TT 2048
#define CC 512
#define NH 8
#define HDIM 64
#define FF 2048
#define VOCAB 32000
#define MT (BB*TT)   // 4096 rows

// ---------------- scratch (device globals; no allocations allowed) ----------
__device__ float g_x   [(size_t)MT*CC];
__device__ float g_ln  [(size_t)MT*CC];
__device__ float g_q   [(size_t)MT*CC];
__device__ float g_k   [(size_t)MT*CC];
__device__ float g_v   [(size_t)MT*CC];
__device__ float g_attn[(size_t)MT*CC];
__device__ float g_ff  [(size_t)MT*FF];
__device__ float g_linv[(size_t)BB*NH*TT];   // per-row 1/l from flash pass

// pre-rounded (tf32) weight copies: [Wq][Wk][Wv][Wo][W1][W2], each all-layers
#define WSEG_P (NLAYER*CC*CC)      // 1048576 (projection matrices)
#define WSEG_F (NLAYER*FF*CC)      // 4194304 (FFN matrices)
__device__ float g_wpack[(size_t)4*WSEG_P + 2*WSEG_F];   // ~50 MB

// ---------------- side stream + events (created at static init, reused) -----
struct StreamInit {
    cudaStream_t s2;
    cudaEvent_t evF[NLAYER], evA[NLAYER];
    StreamInit() {
        cudaStreamCreateWithFlags(&s2, cudaStreamNonBlocking);
        for (int i = 0; i < NLAYER; i++) {
            cudaEventCreateWithFlags(&evF[i], cudaEventDisableTiming);
            cudaEventCreateWithFlags(&evA[i], cudaEventDisableTiming);
        }
    }
};
static StreamInit g_si;

// ---------------- helpers ----------------------------------------------------
__device__ __forceinline__ uint32_t f2tf32(float x) {
    uint32_t u;
    asm("cvt.rna.tf32.f32 %0, %1;" : "=r"(u) : "f"(x));
    return u;
}
__device__ __forceinline__ float rnd_tf32(float x) {
    return __uint_as_float(f2tf32(x));
}

__device__ __forceinline__ float ex2(float x) {
    float y;
    asm("ex2.approx.f32 %0, %1;" : "=f"(y) : "f"(x));
    return y;
}

__device__ __forceinline__ void mma_tf32(float* c, const uint32_t* a, const uint32_t* b) {
    asm volatile(
        "mma.sync.aligned.m16n8k8.row.col.f32.tf32.tf32.f32 "
        "{%0,%1,%2,%3}, {%4,%5,%6,%7}, {%8,%9}, {%0,%1,%2,%3};"
        : "+f"(c[0]), "+f"(c[1]), "+f"(c[2]), "+f"(c[3])
        : "r"(a[0]), "r"(a[1]), "r"(a[2]), "r"(a[3]), "r"(b[0]), "r"(b[1]));
}

__device__ __forceinline__ void cp16(void* sdst, const void* gsrc) {
    unsigned s = (unsigned)__cvta_generic_to_shared(sdst);
    asm volatile("cp.async.cg.shared.global [%0], [%1], 16;\n" :: "r"(s), "l"(gsrc));
}
__device__ __forceinline__ void cp_commit() { asm volatile("cp.async.commit_group;\n"); }
template<int N>
__device__ __forceinline__ void cp_wait() { asm volatile("cp.async.wait_group %0;\n" :: "n"(N)); }

// ---------------- weight pre-rounding (runs once per launch) -----------------
__global__ void round_weights_kernel(const float* __restrict__ wq,
                                     const float* __restrict__ wk,
                                     const float* __restrict__ wv,
                                     const float* __restrict__ wo,
                                     const float* __restrict__ w1,
                                     const float* __restrict__ w2,
                                     float* __restrict__ dst) {
    const int seg = blockIdx.y;
    const float* src;
    size_t off, n;
    switch (seg) {
        case 0: src = wq; off = 0;                          n = WSEG_P; break;
        case 1: src = wk; off = (size_t)WSEG_P;             n = WSEG_P; break;
        case 2: src = wv; off = (size_t)2 * WSEG_P;         n = WSEG_P; break;
        case 3: src = wo; off = (size_t)3 * WSEG_P;         n = WSEG_P; break;
        case 4: src = w1; off = (size_t)4 * WSEG_P;         n = WSEG_F; break;
        default: src = w2; off = (size_t)4 * WSEG_P + WSEG_F; n = WSEG_F; break;
    }
    size_t i4 = (size_t)blockIdx.x * blockDim.x + threadIdx.x;
    if (i4 * 4 >= n) return;
    float4 t = ((const float4*)src)[i4];
    t.x = rnd_tf32(t.x); t.y = rnd_tf32(t.y);
    t.z = rnd_tf32(t.z); t.w = rnd_tf32(t.w);
    ((float4*)(dst + off))[i4] = t;
}

// =============================================================================
// TF32 tensor-core GEMM core (NT). C[M,N] = A[M,K] @ W[N,K]^T
// A and B arrays are PRE-ROUNDED to tf32 -> no cvt in the inner loop.
// CTA tile BM x BN x 32, 256 threads, double-buffered cp.async pipeline.
// EPI: 1 = +bias, 2 = +bias,relu (tf32-rounded output), 3 = +bias,+residual
// =============================================================================
template<int EPI, int BM, int BN>
__device__ __forceinline__ void gemm_core(
    const float* __restrict__ A, const float* __restrict__ B,
    const float* __restrict__ bias, const float* __restrict__ res,
    float* __restrict__ C, int lda, int ldb, int ldc, int K)
{
    constexpr int WM   = BM / 64;
    constexpr int WN   = 8 / WM;
    constexpr int NCW  = BN / WN;
    constexpr int NT_  = NCW / 8;

    extern __shared__ float smem[];
    float* As = smem;                        // 2 * BM * 36
    float* Bs = smem + 2 * BM * 36;          // 2 * BN * 36

    const int tid  = threadIdx.x;
    const int lane = tid & 31, wid = tid >> 5;
    const int warpM = (WM == 1) ? 0 : (wid & 1);
    const int warpN = (WM == 1) ? wid : (wid >> 1);
    const int grp = lane >> 2, qd = lane & 3;

    const int row0 = blockIdx.y * BM;
    const int col0 = blockIdx.x * BN;

    float acc[4][NT_][4];
#pragma unroll
    for (int mt = 0; mt < 4; mt++)
#pragma unroll
        for (int nt = 0; nt < NT_; nt++)
#pragma unroll
            for (int i = 0; i < 4; i++) acc[mt][nt][i] = 0.f;

    auto loadA = [&](int buf, int k0) {
#pragma unroll
        for (int i = 0; i < BM / 32; i++) {
            int idx = i * 256 + tid;
            int r = idx >> 3, c4 = (idx & 7) << 2;
            cp16(As + buf * BM * 36 + r * 36 + c4,
                 A + (size_t)(row0 + r) * lda + k0 + c4);
        }
    };
    auto loadB = [&](int buf, int k0) {
#pragma unroll
        for (int i = 0; i < BN / 32; i++) {
            int idx = i * 256 + tid;
            int r = idx >> 3, c4 = (idx & 7) << 2;
            cp16(Bs + buf * BN * 36 + r * 36 + c4,
                 B + (size_t)(col0 + r) * ldb + k0 + c4);
        }
    };

    auto compute = [&](int buf) {
        const float* Ab = As + buf * BM * 36;
        const float* Bb = Bs + buf * BN * 36;
#pragma unroll
        for (int kt = 0; kt < 4; kt++) {
            uint32_t af[4][4];
#pragma unroll
            for (int mt = 0; mt < 4; mt++) {
                int r0 = warpM * 64 + mt * 16 + grp;
                af[mt][0] = __float_as_uint(Ab[(r0)     * 36 + kt * 8 + qd]);
                af[mt][1] = __float_as_uint(Ab[(r0 + 8) * 36 + kt * 8 + qd]);
                af[mt][2] = __float_as_uint(Ab[(r0)     * 36 + kt * 8 + qd + 4]);
                af[mt][3] = __float_as_uint(Ab[(r0 + 8) * 36 + kt * 8 + qd + 4]);
            }
            uint32_t bf[NT_][2];
#pragma unroll
            for (int nt = 0; nt < NT_; nt++) {
                int nb = warpN * NCW + nt * 8 + grp;
                bf[nt][0] = __float_as_uint(Bb[nb * 36 + kt * 8 + qd]);
                bf[nt][1] = __float_as_uint(Bb[nb * 36 + kt * 8 + qd + 4]);
            }
#pragma unroll
            for (int mt = 0; mt < 4; mt++)
#pragma unroll
                for (int nt = 0; nt < NT_; nt++)
                    mma_tf32(acc[mt][nt], af[mt], bf[nt]);
        }
    };

    const int nk = K >> 5;
    loadA(0, 0);  loadB(0, 0);  cp_commit();
    loadA(1, 32); loadB(1, 32); cp_commit();
    cp_wait<1>();
    __syncthreads();

    for (int kb = 0; kb < nk; kb++) {
        compute(kb & 1);
        __syncthreads();
        if (kb + 2 < nk) { loadA(kb & 1, (kb + 2) * 32); loadB(kb & 1, (kb + 2) * 32); }
        cp_commit();
        cp_wait<1>();
        __syncthreads();
    }

#pragma unroll
    for (int mt = 0; mt < 4; mt++)
#pragma unroll
        for (int nt = 0; nt < NT_; nt++) {
            int row = row0 + warpM * 64 + mt * 16 + grp;
            int col = col0 + warpN * NCW + nt * 8 + qd * 2;
#pragma unroll
            for (int half = 0; half < 2; half++) {
                int r = row + half * 8;
                float v0 = acc[mt][nt][half * 2 + 0];
                float v1 = acc[mt][nt][half * 2 + 1];
                v0 += bias[col]; v1 += bias[col + 1];
                if (EPI == 2) {
                    v0 = rnd_tf32(fmaxf(v0, 0.f));
                    v1 = rnd_tf32(fmaxf(v1, 0.f));
                }
                if (EPI == 3) {
                    v0 += res[(size_t)r * ldc + col];
                    v1 += res[(size_t)r * ldc + col + 1];
                }
                *(float2*)(C + (size_t)r * ldc + col) = make_float2(v0, v1);
            }
        }
}

template<int EPI, int BM, int BN>
__global__ void __launch_bounds__(256, 2)
gemm_tc_kernel(const float* __restrict__ A, const float* __restrict__ B,
               const float* __restrict__ bias, const float* __restrict__ res,
               float* __restrict__ C, int lda, int ldb, int ldc, int K) {
    gemm_core<EPI, BM, BN>(A, B, bias, res, C, lda, ldb, ldc, K);
}

// ---- fused QKV (z selects weight/bias/output); BN=64 to soften wave quant ---
template<int BM, int BN>
__global__ void __launch_bounds__(256, 2)
gemm_qkv_kernel(const float* __restrict__ A,
                const float* __restrict__ Wq, const float* __restrict__ Wk,
                const float* __restrict__ Wv,
                const float* __restrict__ bq, const float* __restrict__ bk,
                const float* __restrict__ bv,
                float* __restrict__ q, float* __restrict__ k, float* __restrict__ v) {
    int z = blockIdx.z;
    const float* B    = z == 0 ? Wq : (z == 1 ? Wk : Wv);
    const float* bias = z == 0 ? bq : (z == 1 ? bk : bv);
    float* C          = z == 0 ? q  : (z == 1 ? k  : v);
    gemm_core<1, BM, BN>(A, B, bias, nullptr, C, CC, CC, CC, CC);
}

// =============================================================================
// Flash attention pass 1, max-free softmax, TRANSPOSED V tile:
// Vt[col][row] stride 56 -> PV B-fragments are LDS.64 (rows 2qd,2qd+1 adjacent).
// Bank pattern (nt*8+grp)*56 + kb*8 + 2qd is conflict-free per 16-lane phase.
// =============================================================================
__global__ void __launch_bounds__(256, 2)
flash_kernel(const float* __restrict__ q, const float* __restrict__ k,
             const float* __restrict__ v, float* __restrict__ o) {
    constexpr int KT = 32, NKT = TT / KT;
    constexpr int KBLK = 68;
    constexpr int PVT = 56;                 // Vt column stride (uints)
    const float SCALEQ = 0.125f * 1.44269504089f;
    extern __shared__ uint32_t usm[];
    uint32_t* Kf = usm;                     // 2 * 32 * 68 = 4352
    uint32_t* Vt = usm + 2 * 32 * KBLK;     // 2 * 64 * 56 = 7168

    const int qt = blockIdx.x, h = blockIdx.y, b = blockIdx.z;
    const int tid = threadIdx.x, lane = tid & 31, w = tid >> 5;
    const int grp = lane >> 2, qd = lane & 3;
    const int rbase = w * 16;

    const float* Qp = q + ((size_t)(b * TT) + qt * 128) * CC + h * 64;
    const float* Kp = k + (size_t)b * TT * CC + h * 64;
    const float* Vp = v + (size_t)b * TT * CC + h * 64;

    uint32_t qf[8][4];
#pragma unroll
    for (int k8 = 0; k8 < 8; k8++) {
        const float* Qr0 = Qp + (size_t)(rbase + grp) * CC + k8 * 8 + qd;
        const float* Qr1 = Qr0 + (size_t)8 * CC;
        qf[k8][0] = f2tf32(Qr0[0] * SCALEQ);
        qf[k8][1] = f2tf32(Qr1[0] * SCALEQ);
        qf[k8][2] = f2tf32(Qr0[4] * SCALEQ);
        qf[k8][3] = f2tf32(Qr1[4] * SCALEQ);
    }

    // K staging (row-major packed, unchanged)
    const int skr = tid >> 3, skc = (tid & 7) * 8;
    // V staging: thread owns column vc, rows vrb..vrb+7 (coalesced per row)
    const int vc = tid & 63, vrb = (tid >> 6) * 8;

    float4 kr0, kr1;
    float vreg[8];
    auto ldgKV = [&](int kt) {
        const float* Kt = Kp + (size_t)(kt * KT + skr) * CC + skc;
        kr0 = *(const float4*)(Kt);
        kr1 = *(const float4*)(Kt + 4);
        const float* Vtg = Vp + (size_t)(kt * KT + vrb) * CC + vc;
#pragma unroll
        for (int i = 0; i < 8; i++) vreg[i] = Vtg[(size_t)i * CC];
    };
    auto stsKV = [&](int buf) {
        uint32_t* kd = Kf + buf * 32 * KBLK
                     + ((skr >> 3) * 8 + (skc >> 3)) * KBLK + (skr & 7) * 8;
        uint4 ua, ub;
        ua.x = f2tf32(kr0.x); ua.y = f2tf32(kr1.x); ua.z = f2tf32(kr0.y); ua.w = f2tf32(kr1.y);
        ub.x = f2tf32(kr0.z); ub.y = f2tf32(kr1.z); ub.z = f2tf32(kr0.w); ub.w = f2tf32(kr1.w);
        *(uint4*)(kd)     = ua;
        *(uint4*)(kd + 4) = ub;
        uint32_t* vd = Vt + buf * 64 * PVT + vc * PVT + vrb;
        uint4 u0, u1;
        u0.x = f2tf32(vreg[0]); u0.y = f2tf32(vreg[1]);
        u0.z = f2tf32(vreg[2]); u0.w = f2tf32(vreg[3]);
        u1.x = f2tf32(vreg[4]); u1.y = f2tf32(vreg[5]);
        u1.z = f2tf32(vreg[6]); u1.w = f2tf32(vreg[7]);
        *(uint4*)(vd)     = u0;
        *(uint4*)(vd + 4) = u1;
    };

    float oacc[8][4];
#pragma unroll
    for (int nt = 0; nt < 8; nt++)
#pragma unroll
        for (int i = 0; i < 4; i++) oacc[nt][i] = 0.f;
    float l0 = 0.f, l1 = 0.f;

    ldgKV(0);
    stsKV(0);
    __syncthreads();

    for (int kt = 0; kt < NKT; kt++) {
        const int buf = kt & 1;
        if (kt + 1 < NKT) ldgKV(kt + 1);

        const uint32_t* Kb = Kf + buf * 32 * KBLK;
        const uint32_t* Vb = Vt + buf * 64 * PVT;

        float sacc[4][4];
#pragma unroll
        for (int nt = 0; nt < 4; nt++)
#pragma unroll
            for (int i = 0; i < 4; i++) sacc[nt][i] = 0.f;
#pragma unroll
        for (int k8 = 0; k8 < 8; k8++) {
#pragma unroll
            for (int nt = 0; nt < 4; nt++) {
                uint2 p = *(const uint2*)(Kb + (nt * 8 + k8) * KBLK + grp * 8 + qd * 2);
                uint32_t bf[2] = {p.x, p.y};
                mma_tf32(sacc[nt], qf[k8], bf);
            }
        }

        float rs0 = 0.f, rs1 = 0.f;
#pragma unroll
        for (int nt = 0; nt < 4; nt++) {
            sacc[nt][0] = ex2(sacc[nt][0]);
            sacc[nt][1] = ex2(sacc[nt][1]);
            sacc[nt][2] = ex2(sacc[nt][2]);
            sacc[nt][3] = ex2(sacc[nt][3]);
            rs0 += sacc[nt][0] + sacc[nt][1];
            rs1 += sacc[nt][2] + sacc[nt][3];
        }
        rs0 += __shfl_xor_sync(0xffffffffu, rs0, 1);
        rs0 += __shfl_xor_sync(0xffffffffu, rs0, 2);
        rs1 += __shfl_xor_sync(0xffffffffu, rs1, 1);
        rs1 += __shfl_xor_sync(0xffffffffu, rs1, 2);
        l0 += rs0;
        l1 += rs1;

        // O += P @ V : S accumulator as A-operand; Vt gives uint2 B-frags
#pragma unroll
        for (int kb = 0; kb < 4; kb++) {
            uint32_t af[4];
            af[0] = f2tf32(sacc[kb][0]);
            af[1] = f2tf32(sacc[kb][2]);
            af[2] = f2tf32(sacc[kb][1]);
            af[3] = f2tf32(sacc[kb][3]);
#pragma unroll
            for (int nt = 0; nt < 8; nt++) {
                uint2 p = *(const uint2*)(Vb + (nt * 8 + grp) * PVT + kb * 8 + 2 * qd);
                uint32_t bf[2] = {p.x, p.y};
                mma_tf32(oacc[nt], af, bf);
            }
        }

        if (kt + 1 < NKT) stsKV(buf ^ 1);
        __syncthreads();
    }

    float i0 = 1.f / l0, i1 = 1.f / l1;
    int row0 = qt * 128 + rbase + grp;
    float* Op = o + ((size_t)(b * TT) + row0) * CC + h * 64;
#pragma unroll
    for (int nt = 0; nt < 8; nt++) {
        *(float2*)(Op + nt * 8 + qd * 2) =
            make_float2(rnd_tf32(oacc[nt][0] * i0), rnd_tf32(oacc[nt][1] * i0));
        *(float2*)(Op + (size_t)8 * CC + nt * 8 + qd * 2) =
            make_float2(rnd_tf32(oacc[nt][2] * i1), rnd_tf32(oacc[nt][3] * i1));
    }
    if (qd == 0) {
        g_linv[(size_t)(b * NH + h) * TT + row0]     = i0;
        g_linv[(size_t)(b * NH + h) * TT + row0 + 8] = i1;
    }
}

// =============================================================================
// Pass 2: head-averaged attention map (validated R11 version), side stream.
// =============================================================================
__global__ void __launch_bounds__(256, 2)
avgmap_kernel(const float* __restrict__ q, const float* __restrict__ k,
              float* __restrict__ avg) {
    constexpr int QBLK = 132, KBLK = 68;
    const float C2 = 0.125f * 1.44269504089f;
    extern __shared__ uint32_t usm[];
    uint32_t* QF = usm;
    uint32_t* KF = usm + 64 * QBLK;
    float* St = (float*)(usm + 64 * QBLK + 64 * KBLK);   // [8][128] inv-l

    const int kc = blockIdx.x, qt = blockIdx.y, b = blockIdx.z;
    const int tid = threadIdx.x, lane = tid & 31, w = tid >> 5;
    const int grp = lane >> 2, qd = lane & 3;
    const int wm = w >> 1, wn = w & 1;

    for (int j = tid; j < NH * 128; j += 256)
        St[j] = g_linv[(size_t)(b * NH + (j >> 7)) * TT + qt * 128 + (j & 127)];

    float aacc[2][4][4];
#pragma unroll
    for (int mt = 0; mt < 2; mt++)
#pragma unroll
        for (int nt = 0; nt < 4; nt++)
#pragma unroll
            for (int i = 0; i < 4; i++) aacc[mt][nt][i] = 0.f;

    const int kkr = tid >> 2, kc0 = (tid & 3) * 16;
    float4 kreg[4];
    auto ldgK = [&](int h) {
        const float* Kp = k + ((size_t)(b * TT) + kc * 64 + kkr) * CC + h * 64 + kc0;
#pragma unroll
        for (int i = 0; i < 4; i++) kreg[i] = *(const float4*)(Kp + i * 4);
    };
    ldgK(0);

    for (int h = 0; h < NH; h++) {
        __syncthreads();
        {
            uint32_t* kb0 = KF + ((kkr >> 3) * 8 + (kc0 >> 3)) * KBLK + (kkr & 7) * 8;
#pragma unroll
            for (int bb = 0; bb < 2; bb++) {
                float4 f0 = kreg[bb * 2], f1 = kreg[bb * 2 + 1];
                uint4 ua, ub;
                ua.x = f2tf32(f0.x); ua.y = f2tf32(f1.x); ua.z = f2tf32(f0.y); ua.w = f2tf32(f1.y);
                ub.x = f2tf32(f0.z); ub.y = f2tf32(f1.z); ub.z = f2tf32(f0.w); ub.w = f2tf32(f1.w);
                *(uint4*)(kb0 + bb * KBLK)     = ua;
                *(uint4*)(kb0 + bb * KBLK + 4) = ub;
            }
        }
        {
            const float* Qp = q + ((size_t)(b * TT) + qt * 128) * CC + h * 64;
#pragma unroll
            for (int i = 0; i < 8; i++) {
                int j = i * 256 + tid;
                int r = j >> 4, c4 = (j & 15) << 2;
                float4 t4 = *(const float4*)(Qp + (size_t)r * CC + c4);
                int blk  = (r >> 4) * 8 + (c4 >> 3);
                int base = blk * QBLK + ((c4 >> 2) & 1) * 2 + ((r >> 3) & 1);
                int ro   = (r & 7) * 4;
                QF[base + (ro + 0) * 4] = f2tf32(t4.x);
                QF[base + (ro + 1) * 4] = f2tf32(t4.y);
                QF[base + (ro + 2) * 4] = f2tf32(t4.z);
                QF[base + (ro + 3) * 4] = f2tf32(t4.w);
            }
        }
        if (h + 1 < NH) ldgK(h + 1);
        __syncthreads();

        float sacc[2][4][4];
#pragma unroll
        for (int mt = 0; mt < 2; mt++)
#pragma unroll
            for (int nt = 0; nt < 4; nt++)
#pragma unroll
                for (int i = 0; i < 4; i++) sacc[mt][nt][i] = 0.f;

#pragma unroll
        for (int k8 = 0; k8 < 8; k8++) {
            uint32_t af[2][4];
#pragma unroll
            for (int mt = 0; mt < 2; mt++) {
                uint4 u = *(const uint4*)(QF + ((wm * 2 + mt) * 8 + k8) * QBLK
                                          + (grp * 4 + qd) * 4);
                af[mt][0] = u.x; af[mt][1] = u.y; af[mt][2] = u.z; af[mt][3] = u.w;
            }
#pragma unroll
            for (int nt = 0; nt < 4; nt++) {
                uint2 p = *(const uint2*)(KF + ((wn * 4 + nt) * 8 + k8) * KBLK
                                          + grp * 8 + qd * 2);
                uint32_t bf[2] = {p.x, p.y};
                mma_tf32(sacc[0][nt], af[0], bf);
                mma_tf32(sacc[1][nt], af[1], bf);
            }
        }

#pragma unroll
        for (int mt = 0; mt < 2; mt++) {
            int r0 = wm * 32 + mt * 16 + grp;
            float il0 = St[h * 128 + r0];
            float il1 = St[h * 128 + r0 + 8];
#pragma unroll
            for (int nt = 0; nt < 4; nt++) {
                aacc[mt][nt][0] += ex2(sacc[mt][nt][0] * C2) * il0;
                aacc[mt][nt][1] += ex2(sacc[mt][nt][1] * C2) * il0;
                aacc[mt][nt][2] += ex2(sacc[mt][nt][2] * C2) * il1;
                aacc[mt][nt][3] += ex2(sacc[mt][nt][3] * C2) * il1;
            }
        }
    }

    const float inv8 = 1.0f / NH;
#pragma unroll
    for (int mt = 0; mt < 2; mt++) {
        int qrow = qt * 128 + wm * 32 + mt * 16 + grp;
        int kcol = kc * 64 + wn * 32;
        float* A0 = avg + ((size_t)(b * TT) + qrow) * TT + kcol;
        float* A1 = A0 + (size_t)8 * TT;
#pragma unroll
        for (int nt = 0; nt < 4; nt++) {
            *(float2*)(A0 + nt * 8 + qd * 2) =
                make_float2(aacc[mt][nt][0] * inv8, aacc[mt][nt][1] * inv8);
            *(float2*)(A1 + nt * 8 + qd * 2) =
                make_float2(aacc[mt][nt][2] * inv8, aacc[mt][nt][3] * inv8);
        }
    }
}

// ---------------- embedding + positional ------------------------------------
__global__ void embed_kernel(const int* __restrict__ x,
                             const float* __restrict__ emb,
                             const float* __restrict__ pos,
                             float* __restrict__ out) {
    int idx = blockIdx.x * blockDim.x + threadIdx.x;
    if (idx >= MT * CC) return;
    int c  = idx % CC;
    int bt = idx / CC;
    int t  = bt % TT;
    int tok = x[bt];
    if (tok < 0) tok = 0;
    if (tok >= VOCAB) tok = VOCAB - 1;
    out[idx] = emb[(size_t)tok * CC + c] + pos[(size_t)t * CC + c];
}

// ---------------- layernorm: one warp per 512-float row ----------------------
template<int RND>
__global__ void ln_kernel(const float* __restrict__ in,
                          const float* __restrict__ g,
                          const float* __restrict__ b,
                          float* __restrict__ out) {
    int row  = blockIdx.x * 8 + (threadIdx.x >> 5);
    int lane = threadIdx.x & 31;
    const float4* xr = (const float4*)(in + (size_t)row * CC);
    float4 v[4];
    float s = 0.f;
#pragma unroll
    for (int i = 0; i < 4; i++) {
        v[i] = xr[i * 32 + lane];
        s += v[i].x + v[i].y + v[i].z + v[i].w;
    }
#pragma unroll
    for (int o = 16; o; o >>= 1) s += __shfl_xor_sync(0xffffffffu, s, o);
    float mean = s * (1.0f / CC);
    float var = 0.f;
#pragma unroll
    for (int i = 0; i < 4; i++) {
        float dx = v[i].x - mean, dy = v[i].y - mean, dz = v[i].z - mean, dw = v[i].w - mean;
        var += dx * dx + dy * dy + dz * dz + dw * dw;
    }
#pragma unroll
    for (int o = 16; o; o >>= 1) var += __shfl_xor_sync(0xffffffffu, var, o);
    float rstd = rsqrtf(var * (1.0f / CC) + 1e-5f);
    float4* op = (float4*)(out + (size_t)row * CC);
    const float4* gp = (const float4*)g;
    const float4* bp = (const float4*)b;
#pragma unroll
    for (int i = 0; i < 4; i++) {
        float4 gg = gp[i * 32 + lane], bb = bp[i * 32 + lane];
        float4 o4;
        o4.x = (v[i].x - mean) * rstd * gg.x + bb.x;
        o4.y = (v[i].y - mean) * rstd * gg.y + bb.y;
        o4.z = (v[i].z - mean) * rstd * gg.z + bb.z;
        o4.w = (v[i].w - mean) * rstd * gg.w + bb.w;
        if (RND) {
            o4.x = rnd_tf32(o4.x); o4.y = rnd_tf32(o4.y);
            o4.z = rnd_tf32(o4.z); o4.w = rnd_tf32(o4.w);
        }
        op[i * 32 + lane] = o4;
    }
}

// ---------------- final pooled output: mean over T of lnf(x) ----------------
__global__ void final_mean_kernel(const float* __restrict__ hln,
                                  float* __restrict__ out) {
    int bd = blockIdx.x;
    int b = bd / CC, d = bd % CC;
    __shared__ float red[256];
    int tid = threadIdx.x;
    float s = 0.f;
    for (int t = tid; t < TT; t += 256)
        s += hln[((size_t)b * TT + t) * CC + d];
    red[tid] = s; __syncthreads();
    for (int o = 128; o > 0; o >>= 1) { if (tid < o) red[tid] += red[tid + o]; __syncthreads(); }
    if (tid == 0) out[bd] = red[0] * (1.0f / TT);
}

// ---------------- launch ------------------------------------------------------
extern "C" void kernel_launch(void* const* d_in, const int* in_sizes, int n_in,
                              void* d_out, int out_size) {
    const int* x      = (const int*)d_in[0];
    const float* emb  = (const float*)d_in[1];
    const float* pos  = (const float*)d_in[2];
    const float* Wq = (const float*)d_in[3],  *bq = (const float*)d_in[4];
    const float* Wk = (const float*)d_in[5],  *bk = (const float*)d_in[6];
    const float* Wv = (const float*)d_in[7],  *bv = (const float*)d_in[8];
    const float* Wo = (const float*)d_in[9],  *bo = (const float*)d_in[10];
    const float* W1 = (const float*)d_in[11], *b1 = (const float*)d_in[12];
    const float* W2 = (const float*)d_in[13], *b2 = (const float*)d_in[14];
    const float* ln1g = (const float*)d_in[15], *ln1b = (const float*)d_in[16];
    const float* ln2g = (const float*)d_in[17], *ln2b = (const float*)d_in[18];
    const float* lnfg = (const float*)d_in[19], *lnfb = (const float*)d_in[20];
    float* out = (float*)d_out;

    float *xb, *lnb, *qb, *kb, *vb, *ab, *fb, *wp;
    cudaGetSymbolAddress((void**)&xb,  g_x);
    cudaGetSymbolAddress((void**)&lnb, g_ln);
    cudaGetSymbolAddress((void**)&qb,  g_q);
    cudaGetSymbolAddress((void**)&kb,  g_k);
    cudaGetSymbolAddress((void**)&vb,  g_v);
    cudaGetSymbolAddress((void**)&ab,  g_attn);
    cudaGetSymbolAddress((void**)&fb,  g_ff);
    cudaGetSymbolAddress((void**)&wp,  g_wpack);

    const float* pWq = wp;
    const float* pWk = wp + (size_t)WSEG_P;
    const float* pWv = wp + (size_t)2 * WSEG_P;
    const float* pWo = wp + (size_t)3 * WSEG_P;
    const float* pW1 = wp + (size_t)4 * WSEG_P;
    const float* pW2 = wp + (size_t)4 * WSEG_P + WSEG_F;

    const int SM_128_128 = (2 * 128 * 36 + 2 * 128 * 36) * 4;           // 73728
    const int SM_128_64  = (2 * 128 * 36 + 2 * 64 * 36) * 4;            // 55296
    const int SM_64_128  = (2 * 64 * 36 + 2 * 128 * 36) * 4;            // 55296
    const int SM_FLASH   = (2 * 32 * 68 + 2 * 64 * 56) * 4;             // 46080
    const int SM_AVG     = (64 * 132 + 64 * 68) * 4 + NH * 128 * 4;     // 55296

    cudaFuncSetAttribute((const void*)gemm_qkv_kernel<128, 64>,
                         cudaFuncAttributeMaxDynamicSharedMemorySize, SM_128_64);
    cudaFuncSetAttribute((const void*)gemm_tc_kernel<2, 128, 128>,
                         cudaFuncAttributeMaxDynamicSharedMemorySize, SM_128_128);
    cudaFuncSetAttribute((const void*)gemm_tc_kernel<3, 64, 128>,
                         cudaFuncAttributeMaxDynamicSharedMemorySize, SM_64_128);
    cudaFuncSetAttribute((const void*)flash_kernel,
                         cudaFuncAttributeMaxDynamicSharedMemorySize, SM_FLASH);
    cudaFuncSetAttribute((const void*)avgmap_kernel,
                         cudaFuncAttributeMaxDynamicSharedMemorySize, SM_AVG);

    const size_t attn_elems = (size_t)NLAYER * BB * TT * TT;
    float* attn_out = out + ((size_t)out_size - attn_elems);

    {
        dim3 gw(WSEG_F / 4 / 256, 6);
        round_weights_kernel<<<gw, 256>>>(Wq, Wk, Wv, Wo, W1, W2, wp);
    }

    embed_kernel<<<(MT * CC + 255) / 256, 256>>>(x, emb, pos, xb);

    for (int l = 0; l < NLAYER; l++) {
        const float* wq = pWq + (size_t)l * CC * CC;
        const float* wk = pWk + (size_t)l * CC * CC;
        const float* wv = pWv + (size_t)l * CC * CC;
        const float* wo = pWo + (size_t)l * CC * CC;
        const float* w1 = pW1 + (size_t)l * FF * CC;
        const float* w2 = pW2 + (size_t)l * CC * FF;

        ln_kernel<1><<<MT / 8, 256>>>(xb, ln1g + (size_t)l * CC, ln1b + (size_t)l * CC, lnb);

        dim3 gqkv(CC / 64, MT / 128, 3);
        gemm_qkv_kernel<128, 64><<<gqkv, 256, SM_128_64>>>(
            lnb, wq, wk, wv,
            bq + (size_t)l * CC, bk + (size_t)l * CC, bv + (size_t)l * CC,
            qb, kb, vb);

        // fused flash attention: O + inv-l (main stream)
        dim3 gfl(TT / 128, NH, BB);
        flash_kernel<<<gfl, 256, SM_FLASH>>>(qb, kb, vb, ab);

        // fork: head-averaged attention map on side stream
        cudaEventRecord(g_si.evF[l], 0);
        cudaStreamWaitEvent(g_si.s2, g_si.evF[l], 0);
        dim3 gav(TT / 64, TT / 128, BB);
        avgmap_kernel<<<gav, 256, SM_AVG, g_si.s2>>>(
            qb, kb, attn_out + (size_t)l * BB * TT * TT);
        cudaEventRecord(g_si.evA[l], g_si.s2);

        // main stream continues: Wo projection + residual
        dim3 gwo(CC / 128, MT / 64, 1);
        gemm_tc_kernel<3, 64, 128><<<gwo, 256, SM_64_128>>>(
            ab, wo, bo + (size_t)l * CC, xb, xb, CC, CC, CC, CC);

        ln_kernel<1><<<MT / 8, 256>>>(xb, ln2g + (size_t)l * CC, ln2b + (size_t)l * CC, lnb);

        dim3 gf1(FF / 128, MT / 128, 1);
        gemm_tc_kernel<2, 128, 128><<<gf1, 256, SM_128_128>>>(
            lnb, w1, b1 + (size_t)l * FF, nullptr, fb, CC, CC, FF, CC);

        dim3 gf2(CC / 128, MT / 64, 1);
        gemm_tc_kernel<3, 64, 128><<<gf2, 256, SM_64_128>>>(
            fb, w2, b2 + (size_t)l * CC, xb, xb, FF, FF, CC, FF);

        // join: next layer's QKV overwrites q/k which avgmap reads
        cudaStreamWaitEvent(0, g_si.evA[l], 0);
    }

    ln_kernel<0><<<MT / 8, 256>>>(xb, lnfg, lnfb, lnb);
    final_mean_kernel<<<BB * CC, 256>>>(lnb, out);
}

// round 14
// speedup vs baseline: 1.0316x; 1.0316x over previous
#include <cuda_runtime.h>
#include <math.h>
#include <stdint.h>

#define NLAYER 4
#define BB 2
#define TT 2048
#define CC 512
#define NH 8
#define HDIM 64
#define FF 2048
#define VOCAB 32000
#define MT (BB*TT)   // 4096 rows

// ---------------- scratch (device globals; no allocations allowed) ----------
__device__ float g_x   [(size_t)MT*CC];
__device__ float g_ln  [(size_t)MT*CC];
__device__ float g_q   [(size_t)MT*CC];
__device__ float g_k   [(size_t)MT*CC];
__device__ float g_v   [(size_t)MT*CC];
__device__ float g_attn[(size_t)MT*CC];
__device__ float g_ff  [(size_t)MT*FF];
__device__ float g_linv[(size_t)BB*NH*TT];   // per-row 1/l from flash pass

// pre-rounded (tf32) weight copies: [Wq][Wk][Wv][Wo][W1][W2], each all-layers
#define WSEG_P (NLAYER*CC*CC)      // 1048576 (projection matrices)
#define WSEG_F (NLAYER*FF*CC)      // 4194304 (FFN matrices)
__device__ float g_wpack[(size_t)4*WSEG_P + 2*WSEG_F];   // ~50 MB

// ---------------- side stream + events (created at static init, reused) -----
struct StreamInit {
    cudaStream_t s2;
    cudaEvent_t evF[NLAYER], evA[NLAYER];
    StreamInit() {
        cudaStreamCreateWithFlags(&s2, cudaStreamNonBlocking);
        for (int i = 0; i < NLAYER; i++) {
            cudaEventCreateWithFlags(&evF[i], cudaEventDisableTiming);
            cudaEventCreateWithFlags(&evA[i], cudaEventDisableTiming);
        }
    }
};
static StreamInit g_si;

// ---------------- helpers ----------------------------------------------------
__device__ __forceinline__ uint32_t f2tf32(float x) {
    uint32_t u;
    asm("cvt.rna.tf32.f32 %0, %1;" : "=r"(u) : "f"(x));
    return u;
}
__device__ __forceinline__ float rnd_tf32(float x) {
    return __uint_as_float(f2tf32(x));
}

__device__ __forceinline__ float ex2(float x) {
    float y;
    asm("ex2.approx.f32 %0, %1;" : "=f"(y) : "f"(x));
    return y;
}

__device__ __forceinline__ void mma_tf32(float* c, const uint32_t* a, const uint32_t* b) {
    asm volatile(
        "mma.sync.aligned.m16n8k8.row.col.f32.tf32.tf32.f32 "
        "{%0,%1,%2,%3}, {%4,%5,%6,%7}, {%8,%9}, {%0,%1,%2,%3};"
        : "+f"(c[0]), "+f"(c[1]), "+f"(c[2]), "+f"(c[3])
        : "r"(a[0]), "r"(a[1]), "r"(a[2]), "r"(a[3]), "r"(b[0]), "r"(b[1]));
}

__device__ __forceinline__ void cp16(void* sdst, const void* gsrc) {
    unsigned s = (unsigned)__cvta_generic_to_shared(sdst);
    asm volatile("cp.async.cg.shared.global [%0], [%1], 16;\n" :: "r"(s), "l"(gsrc));
}
__device__ __forceinline__ void cp_commit() { asm volatile("cp.async.commit_group;\n"); }
template<int N>
__device__ __forceinline__ void cp_wait() { asm volatile("cp.async.wait_group %0;\n" :: "n"(N)); }

// ---------------- weight pre-rounding (runs once per launch) -----------------
__global__ void round_weights_kernel(const float* __restrict__ wq,
                                     const float* __restrict__ wk,
                                     const float* __restrict__ wv,
                                     const float* __restrict__ wo,
                                     const float* __restrict__ w1,
                                     const float* __restrict__ w2,
                                     float* __restrict__ dst) {
    const int seg = blockIdx.y;
    const float* src;
    size_t off, n;
    switch (seg) {
        case 0: src = wq; off = 0;                          n = WSEG_P; break;
        case 1: src = wk; off = (size_t)WSEG_P;             n = WSEG_P; break;
        case 2: src = wv; off = (size_t)2 * WSEG_P;         n = WSEG_P; break;
        case 3: src = wo; off = (size_t)3 * WSEG_P;         n = WSEG_P; break;
        case 4: src = w1; off = (size_t)4 * WSEG_P;         n = WSEG_F; break;
        default: src = w2; off = (size_t)4 * WSEG_P + WSEG_F; n = WSEG_F; break;
    }
    size_t i4 = (size_t)blockIdx.x * blockDim.x + threadIdx.x;
    if (i4 * 4 >= n) return;
    float4 t = ((const float4*)src)[i4];
    t.x = rnd_tf32(t.x); t.y = rnd_tf32(t.y);
    t.z = rnd_tf32(t.z); t.w = rnd_tf32(t.w);
    ((float4*)(dst + off))[i4] = t;
}

// =============================================================================
// TF32 tensor-core GEMM core (NT). C[M,N] = A[M,K] @ W[N,K]^T
// A and B arrays are PRE-ROUNDED to tf32 -> no cvt in the inner loop.
// CTA tile BM x BN x 32, 256 threads, double-buffered cp.async pipeline.
// EPI: 1 = +bias, 2 = +bias,relu (tf32-rounded output), 3 = +bias,+residual
// =============================================================================
template<int EPI, int BM, int BN>
__device__ __forceinline__ void gemm_core(
    const float* __restrict__ A, const float* __restrict__ B,
    const float* __restrict__ bias, const float* __restrict__ res,
    float* __restrict__ C, int lda, int ldb, int ldc, int K)
{
    constexpr int WM   = BM / 64;
    constexpr int WN   = 8 / WM;
    constexpr int NCW  = BN / WN;
    constexpr int NT_  = NCW / 8;

    extern __shared__ float smem[];
    float* As = smem;                        // 2 * BM * 36
    float* Bs = smem + 2 * BM * 36;          // 2 * BN * 36

    const int tid  = threadIdx.x;
    const int lane = tid & 31, wid = tid >> 5;
    const int warpM = (WM == 1) ? 0 : (wid & 1);
    const int warpN = (WM == 1) ? wid : (wid >> 1);
    const int grp = lane >> 2, qd = lane & 3;

    const int row0 = blockIdx.y * BM;
    const int col0 = blockIdx.x * BN;

    float acc[4][NT_][4];
#pragma unroll
    for (int mt = 0; mt < 4; mt++)
#pragma unroll
        for (int nt = 0; nt < NT_; nt++)
#pragma unroll
            for (int i = 0; i < 4; i++) acc[mt][nt][i] = 0.f;

    auto loadA = [&](int buf, int k0) {
#pragma unroll
        for (int i = 0; i < BM / 32; i++) {
            int idx = i * 256 + tid;
            int r = idx >> 3, c4 = (idx & 7) << 2;
            cp16(As + buf * BM * 36 + r * 36 + c4,
                 A + (size_t)(row0 + r) * lda + k0 + c4);
        }
    };
    auto loadB = [&](int buf, int k0) {
#pragma unroll
        for (int i = 0; i < BN / 32; i++) {
            int idx = i * 256 + tid;
            int r = idx >> 3, c4 = (idx & 7) << 2;
            cp16(Bs + buf * BN * 36 + r * 36 + c4,
                 B + (size_t)(col0 + r) * ldb + k0 + c4);
        }
    };

    auto compute = [&](int buf) {
        const float* Ab = As + buf * BM * 36;
        const float* Bb = Bs + buf * BN * 36;
#pragma unroll
        for (int kt = 0; kt < 4; kt++) {
            uint32_t af[4][4];
#pragma unroll
            for (int mt = 0; mt < 4; mt++) {
                int r0 = warpM * 64 + mt * 16 + grp;
                af[mt][0] = __float_as_uint(Ab[(r0)     * 36 + kt * 8 + qd]);
                af[mt][1] = __float_as_uint(Ab[(r0 + 8) * 36 + kt * 8 + qd]);
                af[mt][2] = __float_as_uint(Ab[(r0)     * 36 + kt * 8 + qd + 4]);
                af[mt][3] = __float_as_uint(Ab[(r0 + 8) * 36 + kt * 8 + qd + 4]);
            }
            uint32_t bf[NT_][2];
#pragma unroll
            for (int nt = 0; nt < NT_; nt++) {
                int nb = warpN * NCW + nt * 8 + grp;
                bf[nt][0] = __float_as_uint(Bb[nb * 36 + kt * 8 + qd]);
                bf[nt][1] = __float_as_uint(Bb[nb * 36 + kt * 8 + qd + 4]);
            }
#pragma unroll
            for (int mt = 0; mt < 4; mt++)
#pragma unroll
                for (int nt = 0; nt < NT_; nt++)
                    mma_tf32(acc[mt][nt], af[mt], bf[nt]);
        }
    };

    const int nk = K >> 5;
    loadA(0, 0);  loadB(0, 0);  cp_commit();
    loadA(1, 32); loadB(1, 32); cp_commit();
    cp_wait<1>();
    __syncthreads();

    for (int kb = 0; kb < nk; kb++) {
        compute(kb & 1);
        __syncthreads();
        if (kb + 2 < nk) { loadA(kb & 1, (kb + 2) * 32); loadB(kb & 1, (kb + 2) * 32); }
        cp_commit();
        cp_wait<1>();
        __syncthreads();
    }

#pragma unroll
    for (int mt = 0; mt < 4; mt++)
#pragma unroll
        for (int nt = 0; nt < NT_; nt++) {
            int row = row0 + warpM * 64 + mt * 16 + grp;
            int col = col0 + warpN * NCW + nt * 8 + qd * 2;
#pragma unroll
            for (int half = 0; half < 2; half++) {
                int r = row + half * 8;
                float v0 = acc[mt][nt][half * 2 + 0];
                float v1 = acc[mt][nt][half * 2 + 1];
                v0 += bias[col]; v1 += bias[col + 1];
                if (EPI == 2) {
                    v0 = rnd_tf32(fmaxf(v0, 0.f));
                    v1 = rnd_tf32(fmaxf(v1, 0.f));
                }
                if (EPI == 3) {
                    v0 += res[(size_t)r * ldc + col];
                    v1 += res[(size_t)r * ldc + col + 1];
                }
                *(float2*)(C + (size_t)r * ldc + col) = make_float2(v0, v1);
            }
        }
}

template<int EPI, int BM, int BN>
__global__ void __launch_bounds__(256, 2)
gemm_tc_kernel(const float* __restrict__ A, const float* __restrict__ B,
               const float* __restrict__ bias, const float* __restrict__ res,
               float* __restrict__ C, int lda, int ldb, int ldc, int K) {
    gemm_core<EPI, BM, BN>(A, B, bias, res, C, lda, ldb, ldc, K);
}

// ---- fused QKV (z selects weight/bias/output); BN=128 (validated R12) -------
template<int BM, int BN>
__global__ void __launch_bounds__(256, 2)
gemm_qkv_kernel(const float* __restrict__ A,
                const float* __restrict__ Wq, const float* __restrict__ Wk,
                const float* __restrict__ Wv,
                const float* __restrict__ bq, const float* __restrict__ bk,
                const float* __restrict__ bv,
                float* __restrict__ q, float* __restrict__ k, float* __restrict__ v) {
    int z = blockIdx.z;
    const float* B    = z == 0 ? Wq : (z == 1 ? Wk : Wv);
    const float* bias = z == 0 ? bq : (z == 1 ? bk : bv);
    float* C          = z == 0 ? q  : (z == 1 ? k  : v);
    gemm_core<1, BM, BN>(A, B, bias, nullptr, C, CC, CC, CC, CC);
}

// =============================================================================
// Flash attention pass 1, max-free softmax, TRANSPOSED V tile (R13, kept:
// measured neutral-or-better; fewer issue slots in PV phase).
// =============================================================================
__global__ void __launch_bounds__(256, 2)
flash_kernel(const float* __restrict__ q, const float* __restrict__ k,
             const float* __restrict__ v, float* __restrict__ o) {
    constexpr int KT = 32, NKT = TT / KT;
    constexpr int KBLK = 68;
    constexpr int PVT = 56;                 // Vt column stride (uints)
    const float SCALEQ = 0.125f * 1.44269504089f;
    extern __shared__ uint32_t usm[];
    uint32_t* Kf = usm;                     // 2 * 32 * 68
    uint32_t* Vt = usm + 2 * 32 * KBLK;     // 2 * 64 * 56

    const int qt = blockIdx.x, h = blockIdx.y, b = blockIdx.z;
    const int tid = threadIdx.x, lane = tid & 31, w = tid >> 5;
    const int grp = lane >> 2, qd = lane & 3;
    const int rbase = w * 16;

    const float* Qp = q + ((size_t)(b * TT) + qt * 128) * CC + h * 64;
    const float* Kp = k + (size_t)b * TT * CC + h * 64;
    const float* Vp = v + (size_t)b * TT * CC + h * 64;

    uint32_t qf[8][4];
#pragma unroll
    for (int k8 = 0; k8 < 8; k8++) {
        const float* Qr0 = Qp + (size_t)(rbase + grp) * CC + k8 * 8 + qd;
        const float* Qr1 = Qr0 + (size_t)8 * CC;
        qf[k8][0] = f2tf32(Qr0[0] * SCALEQ);
        qf[k8][1] = f2tf32(Qr1[0] * SCALEQ);
        qf[k8][2] = f2tf32(Qr0[4] * SCALEQ);
        qf[k8][3] = f2tf32(Qr1[4] * SCALEQ);
    }

    const int skr = tid >> 3, skc = (tid & 7) * 8;
    const int vc = tid & 63, vrb = (tid >> 6) * 8;

    float4 kr0, kr1;
    float vreg[8];
    auto ldgKV = [&](int kt) {
        const float* Kt = Kp + (size_t)(kt * KT + skr) * CC + skc;
        kr0 = *(const float4*)(Kt);
        kr1 = *(const float4*)(Kt + 4);
        const float* Vtg = Vp + (size_t)(kt * KT + vrb) * CC + vc;
#pragma unroll
        for (int i = 0; i < 8; i++) vreg[i] = Vtg[(size_t)i * CC];
    };
    auto stsKV = [&](int buf) {
        uint32_t* kd = Kf + buf * 32 * KBLK
                     + ((skr >> 3) * 8 + (skc >> 3)) * KBLK + (skr & 7) * 8;
        uint4 ua, ub;
        ua.x = f2tf32(kr0.x); ua.y = f2tf32(kr1.x); ua.z = f2tf32(kr0.y); ua.w = f2tf32(kr1.y);
        ub.x = f2tf32(kr0.z); ub.y = f2tf32(kr1.z); ub.z = f2tf32(kr0.w); ub.w = f2tf32(kr1.w);
        *(uint4*)(kd)     = ua;
        *(uint4*)(kd + 4) = ub;
        uint32_t* vd = Vt + buf * 64 * PVT + vc * PVT + vrb;
        uint4 u0, u1;
        u0.x = f2tf32(vreg[0]); u0.y = f2tf32(vreg[1]);
        u0.z = f2tf32(vreg[2]); u0.w = f2tf32(vreg[3]);
        u1.x = f2tf32(vreg[4]); u1.y = f2tf32(vreg[5]);
        u1.z = f2tf32(vreg[6]); u1.w = f2tf32(vreg[7]);
        *(uint4*)(vd)     = u0;
        *(uint4*)(vd + 4) = u1;
    };

    float oacc[8][4];
#pragma unroll
    for (int nt = 0; nt < 8; nt++)
#pragma unroll
        for (int i = 0; i < 4; i++) oacc[nt][i] = 0.f;
    float l0 = 0.f, l1 = 0.f;

    ldgKV(0);
    stsKV(0);
    __syncthreads();

    for (int kt = 0; kt < NKT; kt++) {
        const int buf = kt & 1;
        if (kt + 1 < NKT) ldgKV(kt + 1);

        const uint32_t* Kb = Kf + buf * 32 * KBLK;
        const uint32_t* Vb = Vt + buf * 64 * PVT;

        float sacc[4][4];
#pragma unroll
        for (int nt = 0; nt < 4; nt++)
#pragma unroll
            for (int i = 0; i < 4; i++) sacc[nt][i] = 0.f;
#pragma unroll
        for (int k8 = 0; k8 < 8; k8++) {
#pragma unroll
            for (int nt = 0; nt < 4; nt++) {
                uint2 p = *(const uint2*)(Kb + (nt * 8 + k8) * KBLK + grp * 8 + qd * 2);
                uint32_t bf[2] = {p.x, p.y};
                mma_tf32(sacc[nt], qf[k8], bf);
            }
        }

        float rs0 = 0.f, rs1 = 0.f;
#pragma unroll
        for (int nt = 0; nt < 4; nt++) {
            sacc[nt][0] = ex2(sacc[nt][0]);
            sacc[nt][1] = ex2(sacc[nt][1]);
            sacc[nt][2] = ex2(sacc[nt][2]);
            sacc[nt][3] = ex2(sacc[nt][3]);
            rs0 += sacc[nt][0] + sacc[nt][1];
            rs1 += sacc[nt][2] + sacc[nt][3];
        }
        rs0 += __shfl_xor_sync(0xffffffffu, rs0, 1);
        rs0 += __shfl_xor_sync(0xffffffffu, rs0, 2);
        rs1 += __shfl_xor_sync(0xffffffffu, rs1, 1);
        rs1 += __shfl_xor_sync(0xffffffffu, rs1, 2);
        l0 += rs0;
        l1 += rs1;

#pragma unroll
        for (int kb = 0; kb < 4; kb++) {
            uint32_t af[4];
            af[0] = f2tf32(sacc[kb][0]);
            af[1] = f2tf32(sacc[kb][2]);
            af[2] = f2tf32(sacc[kb][1]);
            af[3] = f2tf32(sacc[kb][3]);
#pragma unroll
            for (int nt = 0; nt < 8; nt++) {
                uint2 p = *(const uint2*)(Vb + (nt * 8 + grp) * PVT + kb * 8 + 2 * qd);
                uint32_t bf[2] = {p.x, p.y};
                mma_tf32(oacc[nt], af, bf);
            }
        }

        if (kt + 1 < NKT) stsKV(buf ^ 1);
        __syncthreads();
    }

    float i0 = 1.f / l0, i1 = 1.f / l1;
    int row0 = qt * 128 + rbase + grp;
    float* Op = o + ((size_t)(b * TT) + row0) * CC + h * 64;
#pragma unroll
    for (int nt = 0; nt < 8; nt++) {
        *(float2*)(Op + nt * 8 + qd * 2) =
            make_float2(rnd_tf32(oacc[nt][0] * i0), rnd_tf32(oacc[nt][1] * i0));
        *(float2*)(Op + (size_t)8 * CC + nt * 8 + qd * 2) =
            make_float2(rnd_tf32(oacc[nt][2] * i1), rnd_tf32(oacc[nt][3] * i1));
    }
    if (qd == 0) {
        g_linv[(size_t)(b * NH + h) * TT + row0]     = i0;
        g_linv[(size_t)(b * NH + h) * TT + row0 + 8] = i1;
    }
}

// =============================================================================
// Pass 2: head-averaged attention map (validated R11 version), side stream.
// =============================================================================
__global__ void __launch_bounds__(256, 2)
avgmap_kernel(const float* __restrict__ q, const float* __restrict__ k,
              float* __restrict__ avg) {
    constexpr int QBLK = 132, KBLK = 68;
    const float C2 = 0.125f * 1.44269504089f;
    extern __shared__ uint32_t usm[];
    uint32_t* QF = usm;
    uint32_t* KF = usm + 64 * QBLK;
    float* St = (float*)(usm + 64 * QBLK + 64 * KBLK);   // [8][128] inv-l

    const int kc = blockIdx.x, qt = blockIdx.y, b = blockIdx.z;
    const int tid = threadIdx.x, lane = tid & 31, w = tid >> 5;
    const int grp = lane >> 2, qd = lane & 3;
    const int wm = w >> 1, wn = w & 1;

    for (int j = tid; j < NH * 128; j += 256)
        St[j] = g_linv[(size_t)(b * NH + (j >> 7)) * TT + qt * 128 + (j & 127)];

    float aacc[2][4][4];
#pragma unroll
    for (int mt = 0; mt < 2; mt++)
#pragma unroll
        for (int nt = 0; nt < 4; nt++)
#pragma unroll
            for (int i = 0; i < 4; i++) aacc[mt][nt][i] = 0.f;

    const int kkr = tid >> 2, kc0 = (tid & 3) * 16;
    float4 kreg[4];
    auto ldgK = [&](int h) {
        const float* Kp = k + ((size_t)(b * TT) + kc * 64 + kkr) * CC + h * 64 + kc0;
#pragma unroll
        for (int i = 0; i < 4; i++) kreg[i] = *(const float4*)(Kp + i * 4);
    };
    ldgK(0);

    for (int h = 0; h < NH; h++) {
        __syncthreads();
        {
            uint32_t* kb0 = KF + ((kkr >> 3) * 8 + (kc0 >> 3)) * KBLK + (kkr & 7) * 8;
#pragma unroll
            for (int bb = 0; bb < 2; bb++) {
                float4 f0 = kreg[bb * 2], f1 = kreg[bb * 2 + 1];
                uint4 ua, ub;
                ua.x = f2tf32(f0.x); ua.y = f2tf32(f1.x); ua.z = f2tf32(f0.y); ua.w = f2tf32(f1.y);
                ub.x = f2tf32(f0.z); ub.y = f2tf32(f1.z); ub.z = f2tf32(f0.w); ub.w = f2tf32(f1.w);
                *(uint4*)(kb0 + bb * KBLK)     = ua;
                *(uint4*)(kb0 + bb * KBLK + 4) = ub;
            }
        }
        {
            const float* Qp = q + ((size_t)(b * TT) + qt * 128) * CC + h * 64;
#pragma unroll
            for (int i = 0; i < 8; i++) {
                int j = i * 256 + tid;
                int r = j >> 4, c4 = (j & 15) << 2;
                float4 t4 = *(const float4*)(Qp + (size_t)r * CC + c4);
                int blk  = (r >> 4) * 8 + (c4 >> 3);
                int base = blk * QBLK + ((c4 >> 2) & 1) * 2 + ((r >> 3) & 1);
                int ro   = (r & 7) * 4;
                QF[base + (ro + 0) * 4] = f2tf32(t4.x);
                QF[base + (ro + 1) * 4] = f2tf32(t4.y);
                QF[base + (ro + 2) * 4] = f2tf32(t4.z);
                QF[base + (ro + 3) * 4] = f2tf32(t4.w);
            }
        }
        if (h + 1 < NH) ldgK(h + 1);
        __syncthreads();

        float sacc[2][4][4];
#pragma unroll
        for (int mt = 0; mt < 2; mt++)
#pragma unroll
            for (int nt = 0; nt < 4; nt++)
#pragma unroll
                for (int i = 0; i < 4; i++) sacc[mt][nt][i] = 0.f;

#pragma unroll
        for (int k8 = 0; k8 < 8; k8++) {
            uint32_t af[2][4];
#pragma unroll
            for (int mt = 0; mt < 2; mt++) {
                uint4 u = *(const uint4*)(QF + ((wm * 2 + mt) * 8 + k8) * QBLK
                                          + (grp * 4 + qd) * 4);
                af[mt][0] = u.x; af[mt][1] = u.y; af[mt][2] = u.z; af[mt][3] = u.w;
            }
#pragma unroll
            for (int nt = 0; nt < 4; nt++) {
                uint2 p = *(const uint2*)(KF + ((wn * 4 + nt) * 8 + k8) * KBLK
                                          + grp * 8 + qd * 2);
                uint32_t bf[2] = {p.x, p.y};
                mma_tf32(sacc[0][nt], af[0], bf);
                mma_tf32(sacc[1][nt], af[1], bf);
            }
        }

#pragma unroll
        for (int mt = 0; mt < 2; mt++) {
            int r0 = wm * 32 + mt * 16 + grp;
            float il0 = St[h * 128 + r0];
            float il1 = St[h * 128 + r0 + 8];
#pragma unroll
            for (int nt = 0; nt < 4; nt++) {
                aacc[mt][nt][0] += ex2(sacc[mt][nt][0] * C2) * il0;
                aacc[mt][nt][1] += ex2(sacc[mt][nt][1] * C2) * il0;
                aacc[mt][nt][2] += ex2(sacc[mt][nt][2] * C2) * il1;
                aacc[mt][nt][3] += ex2(sacc[mt][nt][3] * C2) * il1;
            }
        }
    }

    const float inv8 = 1.0f / NH;
#pragma unroll
    for (int mt = 0; mt < 2; mt++) {
        int qrow = qt * 128 + wm * 32 + mt * 16 + grp;
        int kcol = kc * 64 + wn * 32;
        float* A0 = avg + ((size_t)(b * TT) + qrow) * TT + kcol;
        float* A1 = A0 + (size_t)8 * TT;
#pragma unroll
        for (int nt = 0; nt < 4; nt++) {
            *(float2*)(A0 + nt * 8 + qd * 2) =
                make_float2(aacc[mt][nt][0] * inv8, aacc[mt][nt][1] * inv8);
            *(float2*)(A1 + nt * 8 + qd * 2) =
                make_float2(aacc[mt][nt][2] * inv8, aacc[mt][nt][3] * inv8);
        }
    }
}

// ---------------- embedding + positional ------------------------------------
__global__ void embed_kernel(const int* __restrict__ x,
                             const float* __restrict__ emb,
                             const float* __restrict__ pos,
                             float* __restrict__ out) {
    int idx = blockIdx.x * blockDim.x + threadIdx.x;
    if (idx >= MT * CC) return;
    int c  = idx % CC;
    int bt = idx / CC;
    int t  = bt % TT;
    int tok = x[bt];
    if (tok < 0) tok = 0;
    if (tok >= VOCAB) tok = VOCAB - 1;
    out[idx] = emb[(size_t)tok * CC + c] + pos[(size_t)t * CC + c];
}

// ---------------- layernorm: one warp per 512-float row ----------------------
template<int RND>
__global__ void ln_kernel(const float* __restrict__ in,
                          const float* __restrict__ g,
                          const float* __restrict__ b,
                          float* __restrict__ out) {
    int row  = blockIdx.x * 8 + (threadIdx.x >> 5);
    int lane = threadIdx.x & 31;
    const float4* xr = (const float4*)(in + (size_t)row * CC);
    float4 v[4];
    float s = 0.f;
#pragma unroll
    for (int i = 0; i < 4; i++) {
        v[i] = xr[i * 32 + lane];
        s += v[i].x + v[i].y + v[i].z + v[i].w;
    }
#pragma unroll
    for (int o = 16; o; o >>= 1) s += __shfl_xor_sync(0xffffffffu, s, o);
    float mean = s * (1.0f / CC);
    float var = 0.f;
#pragma unroll
    for (int i = 0; i < 4; i++) {
        float dx = v[i].x - mean, dy = v[i].y - mean, dz = v[i].z - mean, dw = v[i].w - mean;
        var += dx * dx + dy * dy + dz * dz + dw * dw;
    }
#pragma unroll
    for (int o = 16; o; o >>= 1) var += __shfl_xor_sync(0xffffffffu, var, o);
    float rstd = rsqrtf(var * (1.0f / CC) + 1e-5f);
    float4* op = (float4*)(out + (size_t)row * CC);
    const float4* gp = (const float4*)g;
    const float4* bp = (const float4*)b;
#pragma unroll
    for (int i = 0; i < 4; i++) {
        float4 gg = gp[i * 32 + lane], bb = bp[i * 32 + lane];
        float4 o4;
        o4.x = (v[i].x - mean) * rstd * gg.x + bb.x;
        o4.y = (v[i].y - mean) * rstd * gg.y + bb.y;
        o4.z = (v[i].z - mean) * rstd * gg.z + bb.z;
        o4.w = (v[i].w - mean) * rstd * gg.w + bb.w;
        if (RND) {
            o4.x = rnd_tf32(o4.x); o4.y = rnd_tf32(o4.y);
            o4.z = rnd_tf32(o4.z); o4.w = rnd_tf32(o4.w);
        }
        op[i * 32 + lane] = o4;
    }
}

// ---------------- final pooled output: mean over T of lnf(x) ----------------
__global__ void final_mean_kernel(const float* __restrict__ hln,
                                  float* __restrict__ out) {
    int bd = blockIdx.x;
    int b = bd / CC, d = bd % CC;
    __shared__ float red[256];
    int tid = threadIdx.x;
    float s = 0.f;
    for (int t = tid; t < TT; t += 256)
        s += hln[((size_t)b * TT + t) * CC + d];
    red[tid] = s; __syncthreads();
    for (int o = 128; o > 0; o >>= 1) { if (tid < o) red[tid] += red[tid + o]; __syncthreads(); }
    if (tid == 0) out[bd] = red[0] * (1.0f / TT);
}

// ---------------- launch ------------------------------------------------------
extern "C" void kernel_launch(void* const* d_in, const int* in_sizes, int n_in,
                              void* d_out, int out_size) {
    const int* x      = (const int*)d_in[0];
    const float* emb  = (const float*)d_in[1];
    const float* pos  = (const float*)d_in[2];
    const float* Wq = (const float*)d_in[3],  *bq = (const float*)d_in[4];
    const float* Wk = (const float*)d_in[5],  *bk = (const float*)d_in[6];
    const float* Wv = (const float*)d_in[7],  *bv = (const float*)d_in[8];
    const float* Wo = (const float*)d_in[9],  *bo = (const float*)d_in[10];
    const float* W1 = (const float*)d_in[11], *b1 = (const float*)d_in[12];
    const float* W2 = (const float*)d_in[13], *b2 = (const float*)d_in[14];
    const float* ln1g = (const float*)d_in[15], *ln1b = (const float*)d_in[16];
    const float* ln2g = (const float*)d_in[17], *ln2b = (const float*)d_in[18];
    const float* lnfg = (const float*)d_in[19], *lnfb = (const float*)d_in[20];
    float* out = (float*)d_out;

    float *xb, *lnb, *qb, *kb, *vb, *ab, *fb, *wp;
    cudaGetSymbolAddress((void**)&xb,  g_x);
    cudaGetSymbolAddress((void**)&lnb, g_ln);
    cudaGetSymbolAddress((void**)&qb,  g_q);
    cudaGetSymbolAddress((void**)&kb,  g_k);
    cudaGetSymbolAddress((void**)&vb,  g_v);
    cudaGetSymbolAddress((void**)&ab,  g_attn);
    cudaGetSymbolAddress((void**)&fb,  g_ff);
    cudaGetSymbolAddress((void**)&wp,  g_wpack);

    const float* pWq = wp;
    const float* pWk = wp + (size_t)WSEG_P;
    const float* pWv = wp + (size_t)2 * WSEG_P;
    const float* pWo = wp + (size_t)3 * WSEG_P;
    const float* pW1 = wp + (size_t)4 * WSEG_P;
    const float* pW2 = wp + (size_t)4 * WSEG_P + WSEG_F;

    const int SM_128_128 = (2 * 128 * 36 + 2 * 128 * 36) * 4;           // 73728
    const int SM_64_128  = (2 * 64 * 36 + 2 * 128 * 36) * 4;            // 55296
    const int SM_FLASH   = (2 * 32 * 68 + 2 * 64 * 56) * 4;             // 46080
    const int SM_AVG     = (64 * 132 + 64 * 68) * 4 + NH * 128 * 4;     // 55296

    cudaFuncSetAttribute((const void*)gemm_qkv_kernel<128, 128>,
                         cudaFuncAttributeMaxDynamicSharedMemorySize, SM_128_128);
    cudaFuncSetAttribute((const void*)gemm_tc_kernel<2, 128, 128>,
                         cudaFuncAttributeMaxDynamicSharedMemorySize, SM_128_128);
    cudaFuncSetAttribute((const void*)gemm_tc_kernel<3, 64, 128>,
                         cudaFuncAttributeMaxDynamicSharedMemorySize, SM_64_128);
    cudaFuncSetAttribute((const void*)flash_kernel,
                         cudaFuncAttributeMaxDynamicSharedMemorySize, SM_FLASH);
    cudaFuncSetAttribute((const void*)avgmap_kernel,
                         cudaFuncAttributeMaxDynamicSharedMemorySize, SM_AVG);

    const size_t attn_elems = (size_t)NLAYER * BB * TT * TT;
    float* attn_out = out + ((size_t)out_size - attn_elems);

    {
        dim3 gw(WSEG_F / 4 / 256, 6);
        round_weights_kernel<<<gw, 256>>>(Wq, Wk, Wv, Wo, W1, W2, wp);
    }

    embed_kernel<<<(MT * CC + 255) / 256, 256>>>(x, emb, pos, xb);

    for (int l = 0; l < NLAYER; l++) {
        const float* wq = pWq + (size_t)l * CC * CC;
        const float* wk = pWk + (size_t)l * CC * CC;
        const float* wv = pWv + (size_t)l * CC * CC;
        const float* wo = pWo + (size_t)l * CC * CC;
        const float* w1 = pW1 + (size_t)l * FF * CC;
        const float* w2 = pW2 + (size_t)l * CC * FF;

        ln_kernel<1><<<MT / 8, 256>>>(xb, ln1g + (size_t)l * CC, ln1b + (size_t)l * CC, lnb);

        dim3 gqkv(CC / 128, MT / 128, 3);
        gemm_qkv_kernel<128, 128><<<gqkv, 256, SM_128_128>>>(
            lnb, wq, wk, wv,
            bq + (size_t)l * CC, bk + (size_t)l * CC, bv + (size_t)l * CC,
            qb, kb, vb);

        // fused flash attention: O + inv-l (main stream)
        dim3 gfl(TT / 128, NH, BB);
        flash_kernel<<<gfl, 256, SM_FLASH>>>(qb, kb, vb, ab);

        // fork: head-averaged attention map on side stream
        cudaEventRecord(g_si.evF[l], 0);
        cudaStreamWaitEvent(g_si.s2, g_si.evF[l], 0);
        dim3 gav(TT / 64, TT / 128, BB);
        avgmap_kernel<<<gav, 256, SM_AVG, g_si.s2>>>(
            qb, kb, attn_out + (size_t)l * BB * TT * TT);
        cudaEventRecord(g_si.evA[l], g_si.s2);

        // main stream continues: Wo projection + residual
        dim3 gwo(CC / 128, MT / 64, 1);
        gemm_tc_kernel<3, 64, 128><<<gwo, 256, SM_64_128>>>(
            ab, wo, bo + (size_t)l * CC, xb, xb, CC, CC, CC, CC);

        ln_kernel<1><<<MT / 8, 256>>>(xb, ln2g + (size_t)l * CC, ln2b + (size_t)l * CC, lnb);

        dim3 gf1(FF / 128, MT / 128, 1);
        gemm_tc_kernel<2, 128, 128><<<gf1, 256, SM_128_128>>>(
            lnb, w1, b1 + (size_t)l * FF, nullptr, fb, CC, CC, FF, CC);

        dim3 gf2(CC / 128, MT / 64, 1);
        gemm_tc_kernel<3, 64, 128><<<gf2, 256, SM_64_128>>>(
            fb, w2, b2 + (size_t)l * CC, xb, xb, FF, FF, CC, FF);

        // join: next layer's QKV overwrites q/k which avgmap reads
        cudaStreamWaitEvent(0, g_si.evA[l], 0);
    }

    ln_kernel<0><<<MT / 8, 256>>>(xb, lnfg, lnfb, lnb);
    final_mean_kernel<<<BB * CC, 256>>>(lnb, out);
}

// round 15
// speedup vs baseline: 1.0319x; 1.0003x over previous
#include <cuda_runtime.h>
#include <math.h>
#include <stdint.h>

#define NLAYER 4
#define BB 2
#define TT 2048
#define CC 512
#define NH 8
#define HDIM 64
#define FF 2048
#define VOCAB 32000
#define MT (BB*TT)   // 4096 rows

// ---------------- scratch (device globals; no allocations allowed) ----------
__device__ float g_x   [(size_t)MT*CC];
__device__ float g_ln  [(size_t)MT*CC];
__device__ float g_q   [(size_t)MT*CC];
__device__ float g_k   [(size_t)MT*CC];
__device__ float g_v   [(size_t)MT*CC];
__device__ float g_attn[(size_t)MT*CC];
__device__ float g_ff  [(size_t)MT*FF];
__device__ float g_linv[(size_t)BB*NH*TT];   // per-row 1/l from flash pass

// pre-rounded (tf32) weight copies: [Wq][Wk][Wv][Wo][W1][W2], each all-layers
#define WSEG_P (NLAYER*CC*CC)      // 1048576 (projection matrices)
#define WSEG_F (NLAYER*FF*CC)      // 4194304 (FFN matrices)
__device__ float g_wpack[(size_t)4*WSEG_P + 2*WSEG_F];   // ~50 MB

// ---------------- side stream + events (created at static init, reused) -----
struct StreamInit {
    cudaStream_t s2;
    cudaEvent_t evF[NLAYER], evA[NLAYER];
    StreamInit() {
        cudaStreamCreateWithFlags(&s2, cudaStreamNonBlocking);
        for (int i = 0; i < NLAYER; i++) {
            cudaEventCreateWithFlags(&evF[i], cudaEventDisableTiming);
            cudaEventCreateWithFlags(&evA[i], cudaEventDisableTiming);
        }
    }
};
static StreamInit g_si;

// ---------------- helpers ----------------------------------------------------
__device__ __forceinline__ uint32_t f2tf32(float x) {
    uint32_t u;
    asm("cvt.rna.tf32.f32 %0, %1;" : "=r"(u) : "f"(x));
    return u;
}
__device__ __forceinline__ float rnd_tf32(float x) {
    return __uint_as_float(f2tf32(x));
}

__device__ __forceinline__ float ex2(float x) {
    float y;
    asm("ex2.approx.f32 %0, %1;" : "=f"(y) : "f"(x));
    return y;
}

__device__ __forceinline__ void mma_tf32(float* c, const uint32_t* a, const uint32_t* b) {
    asm volatile(
        "mma.sync.aligned.m16n8k8.row.col.f32.tf32.tf32.f32 "
        "{%0,%1,%2,%3}, {%4,%5,%6,%7}, {%8,%9}, {%0,%1,%2,%3};"
        : "+f"(c[0]), "+f"(c[1]), "+f"(c[2]), "+f"(c[3])
        : "r"(a[0]), "r"(a[1]), "r"(a[2]), "r"(a[3]), "r"(b[0]), "r"(b[1]));
}

__device__ __forceinline__ void cp16(void* sdst, const void* gsrc) {
    unsigned s = (unsigned)__cvta_generic_to_shared(sdst);
    asm volatile("cp.async.cg.shared.global [%0], [%1], 16;\n" :: "r"(s), "l"(gsrc));
}
__device__ __forceinline__ void cp_commit() { asm volatile("cp.async.commit_group;\n"); }
template<int N>
__device__ __forceinline__ void cp_wait() { asm volatile("cp.async.wait_group %0;\n" :: "n"(N)); }

// ---------------- weight pre-rounding (runs once per launch) -----------------
__global__ void round_weights_kernel(const float* __restrict__ wq,
                                     const float* __restrict__ wk,
                                     const float* __restrict__ wv,
                                     const float* __restrict__ wo,
                                     const float* __restrict__ w1,
                                     const float* __restrict__ w2,
                                     float* __restrict__ dst) {
    const int seg = blockIdx.y;
    const float* src;
    size_t off, n;
    switch (seg) {
        case 0: src = wq; off = 0;                          n = WSEG_P; break;
        case 1: src = wk; off = (size_t)WSEG_P;             n = WSEG_P; break;
        case 2: src = wv; off = (size_t)2 * WSEG_P;         n = WSEG_P; break;
        case 3: src = wo; off = (size_t)3 * WSEG_P;         n = WSEG_P; break;
        case 4: src = w1; off = (size_t)4 * WSEG_P;         n = WSEG_F; break;
        default: src = w2; off = (size_t)4 * WSEG_P + WSEG_F; n = WSEG_F; break;
    }
    size_t i4 = (size_t)blockIdx.x * blockDim.x + threadIdx.x;
    if (i4 * 4 >= n) return;
    float4 t = ((const float4*)src)[i4];
    t.x = rnd_tf32(t.x); t.y = rnd_tf32(t.y);
    t.z = rnd_tf32(t.z); t.w = rnd_tf32(t.w);
    ((float4*)(dst + off))[i4] = t;
}

// =============================================================================
// TF32 tensor-core GEMM core (NT). C[M,N] = A[M,K] @ W[N,K]^T
// A and B arrays are PRE-ROUNDED to tf32 -> no cvt in the inner loop.
// CTA tile BM x BN x 32, 256 threads, 3-STAGE cp.async pipeline with a
// SINGLE __syncthreads per chunk (sync proves compute(kb-1) done, so buffer
// (kb+2)%3 == (kb-1)%3 is safe to overwrite after it).
// EPI: 1 = +bias, 2 = +bias,relu (tf32-rounded output), 3 = +bias,+residual
// =============================================================================
template<int EPI, int BM, int BN>
__device__ __forceinline__ void gemm_core(
    const float* __restrict__ A, const float* __restrict__ B,
    const float* __restrict__ bias, const float* __restrict__ res,
    float* __restrict__ C, int lda, int ldb, int ldc, int K)
{
    constexpr int WM   = BM / 64;
    constexpr int WN   = 8 / WM;
    constexpr int NCW  = BN / WN;
    constexpr int NT_  = NCW / 8;
    constexpr int ASZ  = BM * 36;
    constexpr int BSZ  = BN * 36;

    extern __shared__ float smem[];
    float* As = smem;                        // 3 * ASZ
    float* Bs = smem + 3 * ASZ;              // 3 * BSZ

    const int tid  = threadIdx.x;
    const int lane = tid & 31, wid = tid >> 5;
    const int warpM = (WM == 1) ? 0 : (wid & 1);
    const int warpN = (WM == 1) ? wid : (wid >> 1);
    const int grp = lane >> 2, qd = lane & 3;

    const int row0 = blockIdx.y * BM;
    const int col0 = blockIdx.x * BN;

    float acc[4][NT_][4];
#pragma unroll
    for (int mt = 0; mt < 4; mt++)
#pragma unroll
        for (int nt = 0; nt < NT_; nt++)
#pragma unroll
            for (int i = 0; i < 4; i++) acc[mt][nt][i] = 0.f;

    auto loadA = [&](int buf, int k0) {
#pragma unroll
        for (int i = 0; i < BM / 32; i++) {
            int idx = i * 256 + tid;
            int r = idx >> 3, c4 = (idx & 7) << 2;
            cp16(As + buf * ASZ + r * 36 + c4,
                 A + (size_t)(row0 + r) * lda + k0 + c4);
        }
    };
    auto loadB = [&](int buf, int k0) {
#pragma unroll
        for (int i = 0; i < BN / 32; i++) {
            int idx = i * 256 + tid;
            int r = idx >> 3, c4 = (idx & 7) << 2;
            cp16(Bs + buf * BSZ + r * 36 + c4,
                 B + (size_t)(col0 + r) * ldb + k0 + c4);
        }
    };

    auto compute = [&](int buf) {
        const float* Ab = As + buf * ASZ;
        const float* Bb = Bs + buf * BSZ;
#pragma unroll
        for (int kt = 0; kt < 4; kt++) {
            uint32_t af[4][4];
#pragma unroll
            for (int mt = 0; mt < 4; mt++) {
                int r0 = warpM * 64 + mt * 16 + grp;
                af[mt][0] = __float_as_uint(Ab[(r0)     * 36 + kt * 8 + qd]);
                af[mt][1] = __float_as_uint(Ab[(r0 + 8) * 36 + kt * 8 + qd]);
                af[mt][2] = __float_as_uint(Ab[(r0)     * 36 + kt * 8 + qd + 4]);
                af[mt][3] = __float_as_uint(Ab[(r0 + 8) * 36 + kt * 8 + qd + 4]);
            }
            uint32_t bf[NT_][2];
#pragma unroll
            for (int nt = 0; nt < NT_; nt++) {
                int nb = warpN * NCW + nt * 8 + grp;
                bf[nt][0] = __float_as_uint(Bb[nb * 36 + kt * 8 + qd]);
                bf[nt][1] = __float_as_uint(Bb[nb * 36 + kt * 8 + qd + 4]);
            }
#pragma unroll
            for (int mt = 0; mt < 4; mt++)
#pragma unroll
                for (int nt = 0; nt < NT_; nt++)
                    mma_tf32(acc[mt][nt], af[mt], bf[nt]);
        }
    };

    const int nk = K >> 5;
    loadA(0, 0);  loadB(0, 0);  cp_commit();
    loadA(1, 32); loadB(1, 32); cp_commit();

    int buf = 0;           // kb % 3
    int nbuf = 2;          // (kb+2) % 3
    for (int kb = 0; kb < nk; kb++) {
        cp_wait<1>();      // chunk kb complete (chunk kb+1 may be in flight)
        __syncthreads();   // also proves compute(kb-1) done -> nbuf reusable
        int nb = kb + 2;
        if (nb < nk) { loadA(nbuf, nb * 32); loadB(nbuf, nb * 32); }
        cp_commit();       // one group per iteration keeps wait counts aligned
        compute(buf);
        buf = (buf == 2) ? 0 : buf + 1;
        nbuf = (nbuf == 2) ? 0 : nbuf + 1;
    }

#pragma unroll
    for (int mt = 0; mt < 4; mt++)
#pragma unroll
        for (int nt = 0; nt < NT_; nt++) {
            int row = row0 + warpM * 64 + mt * 16 + grp;
            int col = col0 + warpN * NCW + nt * 8 + qd * 2;
#pragma unroll
            for (int half = 0; half < 2; half++) {
                int r = row + half * 8;
                float v0 = acc[mt][nt][half * 2 + 0];
                float v1 = acc[mt][nt][half * 2 + 1];
                v0 += bias[col]; v1 += bias[col + 1];
                if (EPI == 2) {
                    v0 = rnd_tf32(fmaxf(v0, 0.f));
                    v1 = rnd_tf32(fmaxf(v1, 0.f));
                }
                if (EPI == 3) {
                    v0 += res[(size_t)r * ldc + col];
                    v1 += res[(size_t)r * ldc + col + 1];
                }
                *(float2*)(C + (size_t)r * ldc + col) = make_float2(v0, v1);
            }
        }
}

template<int EPI, int BM, int BN>
__global__ void __launch_bounds__(256, 2)
gemm_tc_kernel(const float* __restrict__ A, const float* __restrict__ B,
               const float* __restrict__ bias, const float* __restrict__ res,
               float* __restrict__ C, int lda, int ldb, int ldc, int K) {
    gemm_core<EPI, BM, BN>(A, B, bias, res, C, lda, ldb, ldc, K);
}

// ---- fused QKV (z selects weight/bias/output); BN=128 (validated) -----------
template<int BM, int BN>
__global__ void __launch_bounds__(256, 2)
gemm_qkv_kernel(const float* __restrict__ A,
                const float* __restrict__ Wq, const float* __restrict__ Wk,
                const float* __restrict__ Wv,
                const float* __restrict__ bq, const float* __restrict__ bk,
                const float* __restrict__ bv,
                float* __restrict__ q, float* __restrict__ k, float* __restrict__ v) {
    int z = blockIdx.z;
    const float* B    = z == 0 ? Wq : (z == 1 ? Wk : Wv);
    const float* bias = z == 0 ? bq : (z == 1 ? bk : bv);
    float* C          = z == 0 ? q  : (z == 1 ? k  : v);
    gemm_core<1, BM, BN>(A, B, bias, nullptr, C, CC, CC, CC, CC);
}

// =============================================================================
// Flash attention pass 1 (validated R13/R14: max-free softmax, transposed V).
// =============================================================================
__global__ void __launch_bounds__(256, 2)
flash_kernel(const float* __restrict__ q, const float* __restrict__ k,
             const float* __restrict__ v, float* __restrict__ o) {
    constexpr int KT = 32, NKT = TT / KT;
    constexpr int KBLK = 68;
    constexpr int PVT = 56;
    const float SCALEQ = 0.125f * 1.44269504089f;
    extern __shared__ uint32_t usm[];
    uint32_t* Kf = usm;                     // 2 * 32 * 68
    uint32_t* Vt = usm + 2 * 32 * KBLK;     // 2 * 64 * 56

    const int qt = blockIdx.x, h = blockIdx.y, b = blockIdx.z;
    const int tid = threadIdx.x, lane = tid & 31, w = tid >> 5;
    const int grp = lane >> 2, qd = lane & 3;
    const int rbase = w * 16;

    const float* Qp = q + ((size_t)(b * TT) + qt * 128) * CC + h * 64;
    const float* Kp = k + (size_t)b * TT * CC + h * 64;
    const float* Vp = v + (size_t)b * TT * CC + h * 64;

    uint32_t qf[8][4];
#pragma unroll
    for (int k8 = 0; k8 < 8; k8++) {
        const float* Qr0 = Qp + (size_t)(rbase + grp) * CC + k8 * 8 + qd;
        const float* Qr1 = Qr0 + (size_t)8 * CC;
        qf[k8][0] = f2tf32(Qr0[0] * SCALEQ);
        qf[k8][1] = f2tf32(Qr1[0] * SCALEQ);
        qf[k8][2] = f2tf32(Qr0[4] * SCALEQ);
        qf[k8][3] = f2tf32(Qr1[4] * SCALEQ);
    }

    const int skr = tid >> 3, skc = (tid & 7) * 8;
    const int vc = tid & 63, vrb = (tid >> 6) * 8;

    float4 kr0, kr1;
    float vreg[8];
    auto ldgKV = [&](int kt) {
        const float* Kt = Kp + (size_t)(kt * KT + skr) * CC + skc;
        kr0 = *(const float4*)(Kt);
        kr1 = *(const float4*)(Kt + 4);
        const float* Vtg = Vp + (size_t)(kt * KT + vrb) * CC + vc;
#pragma unroll
        for (int i = 0; i < 8; i++) vreg[i] = Vtg[(size_t)i * CC];
    };
    auto stsKV = [&](int buf) {
        uint32_t* kd = Kf + buf * 32 * KBLK
                     + ((skr >> 3) * 8 + (skc >> 3)) * KBLK + (skr & 7) * 8;
        uint4 ua, ub;
        ua.x = f2tf32(kr0.x); ua.y = f2tf32(kr1.x); ua.z = f2tf32(kr0.y); ua.w = f2tf32(kr1.y);
        ub.x = f2tf32(kr0.z); ub.y = f2tf32(kr1.z); ub.z = f2tf32(kr0.w); ub.w = f2tf32(kr1.w);
        *(uint4*)(kd)     = ua;
        *(uint4*)(kd + 4) = ub;
        uint32_t* vd = Vt + buf * 64 * PVT + vc * PVT + vrb;
        uint4 u0, u1;
        u0.x = f2tf32(vreg[0]); u0.y = f2tf32(vreg[1]);
        u0.z = f2tf32(vreg[2]); u0.w = f2tf32(vreg[3]);
        u1.x = f2tf32(vreg[4]); u1.y = f2tf32(vreg[5]);
        u1.z = f2tf32(vreg[6]); u1.w = f2tf32(vreg[7]);
        *(uint4*)(vd)     = u0;
        *(uint4*)(vd + 4) = u1;
    };

    float oacc[8][4];
#pragma unroll
    for (int nt = 0; nt < 8; nt++)
#pragma unroll
        for (int i = 0; i < 4; i++) oacc[nt][i] = 0.f;
    float l0 = 0.f, l1 = 0.f;

    ldgKV(0);
    stsKV(0);
    __syncthreads();

    for (int kt = 0; kt < NKT; kt++) {
        const int buf = kt & 1;
        if (kt + 1 < NKT) ldgKV(kt + 1);

        const uint32_t* Kb = Kf + buf * 32 * KBLK;
        const uint32_t* Vb = Vt + buf * 64 * PVT;

        float sacc[4][4];
#pragma unroll
        for (int nt = 0; nt < 4; nt++)
#pragma unroll
            for (int i = 0; i < 4; i++) sacc[nt][i] = 0.f;
#pragma unroll
        for (int k8 = 0; k8 < 8; k8++) {
#pragma unroll
            for (int nt = 0; nt < 4; nt++) {
                uint2 p = *(const uint2*)(Kb + (nt * 8 + k8) * KBLK + grp * 8 + qd * 2);
                uint32_t bf[2] = {p.x, p.y};
                mma_tf32(sacc[nt], qf[k8], bf);
            }
        }

        float rs0 = 0.f, rs1 = 0.f;
#pragma unroll
        for (int nt = 0; nt < 4; nt++) {
            sacc[nt][0] = ex2(sacc[nt][0]);
            sacc[nt][1] = ex2(sacc[nt][1]);
            sacc[nt][2] = ex2(sacc[nt][2]);
            sacc[nt][3] = ex2(sacc[nt][3]);
            rs0 += sacc[nt][0] + sacc[nt][1];
            rs1 += sacc[nt][2] + sacc[nt][3];
        }
        rs0 += __shfl_xor_sync(0xffffffffu, rs0, 1);
        rs0 += __shfl_xor_sync(0xffffffffu, rs0, 2);
        rs1 += __shfl_xor_sync(0xffffffffu, rs1, 1);
        rs1 += __shfl_xor_sync(0xffffffffu, rs1, 2);
        l0 += rs0;
        l1 += rs1;

#pragma unroll
        for (int kb = 0; kb < 4; kb++) {
            uint32_t af[4];
            af[0] = f2tf32(sacc[kb][0]);
            af[1] = f2tf32(sacc[kb][2]);
            af[2] = f2tf32(sacc[kb][1]);
            af[3] = f2tf32(sacc[kb][3]);
#pragma unroll
            for (int nt = 0; nt < 8; nt++) {
                uint2 p = *(const uint2*)(Vb + (nt * 8 + grp) * PVT + kb * 8 + 2 * qd);
                uint32_t bf[2] = {p.x, p.y};
                mma_tf32(oacc[nt], af, bf);
            }
        }

        if (kt + 1 < NKT) stsKV(buf ^ 1);
        __syncthreads();
    }

    float i0 = 1.f / l0, i1 = 1.f / l1;
    int row0 = qt * 128 + rbase + grp;
    float* Op = o + ((size_t)(b * TT) + row0) * CC + h * 64;
#pragma unroll
    for (int nt = 0; nt < 8; nt++) {
        *(float2*)(Op + nt * 8 + qd * 2) =
            make_float2(rnd_tf32(oacc[nt][0] * i0), rnd_tf32(oacc[nt][1] * i0));
        *(float2*)(Op + (size_t)8 * CC + nt * 8 + qd * 2) =
            make_float2(rnd_tf32(oacc[nt][2] * i1), rnd_tf32(oacc[nt][3] * i1));
    }
    if (qd == 0) {
        g_linv[(size_t)(b * NH + h) * TT + row0]     = i0;
        g_linv[(size_t)(b * NH + h) * TT + row0 + 8] = i1;
    }
}

// =============================================================================
// Pass 2: head-averaged attention map (validated R11 version), side stream.
// =============================================================================
__global__ void __launch_bounds__(256, 2)
avgmap_kernel(const float* __restrict__ q, const float* __restrict__ k,
              float* __restrict__ avg) {
    constexpr int QBLK = 132, KBLK = 68;
    const float C2 = 0.125f * 1.44269504089f;
    extern __shared__ uint32_t usm[];
    uint32_t* QF = usm;
    uint32_t* KF = usm + 64 * QBLK;
    float* St = (float*)(usm + 64 * QBLK + 64 * KBLK);   // [8][128] inv-l

    const int kc = blockIdx.x, qt = blockIdx.y, b = blockIdx.z;
    const int tid = threadIdx.x, lane = tid & 31, w = tid >> 5;
    const int grp = lane >> 2, qd = lane & 3;
    const int wm = w >> 1, wn = w & 1;

    for (int j = tid; j < NH * 128; j += 256)
        St[j] = g_linv[(size_t)(b * NH + (j >> 7)) * TT + qt * 128 + (j & 127)];

    float aacc[2][4][4];
#pragma unroll
    for (int mt = 0; mt < 2; mt++)
#pragma unroll
        for (int nt = 0; nt < 4; nt++)
#pragma unroll
            for (int i = 0; i < 4; i++) aacc[mt][nt][i] = 0.f;

    const int kkr = tid >> 2, kc0 = (tid & 3) * 16;
    float4 kreg[4];
    auto ldgK = [&](int h) {
        const float* Kp = k + ((size_t)(b * TT) + kc * 64 + kkr) * CC + h * 64 + kc0;
#pragma unroll
        for (int i = 0; i < 4; i++) kreg[i] = *(const float4*)(Kp + i * 4);
    };
    ldgK(0);

    for (int h = 0; h < NH; h++) {
        __syncthreads();
        {
            uint32_t* kb0 = KF + ((kkr >> 3) * 8 + (kc0 >> 3)) * KBLK + (kkr & 7) * 8;
#pragma unroll
            for (int bb = 0; bb < 2; bb++) {
                float4 f0 = kreg[bb * 2], f1 = kreg[bb * 2 + 1];
                uint4 ua, ub;
                ua.x = f2tf32(f0.x); ua.y = f2tf32(f1.x); ua.z = f2tf32(f0.y); ua.w = f2tf32(f1.y);
                ub.x = f2tf32(f0.z); ub.y = f2tf32(f1.z); ub.z = f2tf32(f0.w); ub.w = f2tf32(f1.w);
                *(uint4*)(kb0 + bb * KBLK)     = ua;
                *(uint4*)(kb0 + bb * KBLK + 4) = ub;
            }
        }
        {
            const float* Qp = q + ((size_t)(b * TT) + qt * 128) * CC + h * 64;
#pragma unroll
            for (int i = 0; i < 8; i++) {
                int j = i * 256 + tid;
                int r = j >> 4, c4 = (j & 15) << 2;
                float4 t4 = *(const float4*)(Qp + (size_t)r * CC + c4);
                int blk  = (r >> 4) * 8 + (c4 >> 3);
                int base = blk * QBLK + ((c4 >> 2) & 1) * 2 + ((r >> 3) & 1);
                int ro   = (r & 7) * 4;
                QF[base + (ro + 0) * 4] = f2tf32(t4.x);
                QF[base + (ro + 1) * 4] = f2tf32(t4.y);
                QF[base + (ro + 2) * 4] = f2tf32(t4.z);
                QF[base + (ro + 3) * 4] = f2tf32(t4.w);
            }
        }
        if (h + 1 < NH) ldgK(h + 1);
        __syncthreads();

        float sacc[2][4][4];
#pragma unroll
        for (int mt = 0; mt < 2; mt++)
#pragma unroll
            for (int nt = 0; nt < 4; nt++)
#pragma unroll
                for (int i = 0; i < 4; i++) sacc[mt][nt][i] = 0.f;

#pragma unroll
        for (int k8 = 0; k8 < 8; k8++) {
            uint32_t af[2][4];
#pragma unroll
            for (int mt = 0; mt < 2; mt++) {
                uint4 u = *(const uint4*)(QF + ((wm * 2 + mt) * 8 + k8) * QBLK
                                          + (grp * 4 + qd) * 4);
                af[mt][0] = u.x; af[mt][1] = u.y; af[mt][2] = u.z; af[mt][3] = u.w;
            }
#pragma unroll
            for (int nt = 0; nt < 4; nt++) {
                uint2 p = *(const uint2*)(KF + ((wn * 4 + nt) * 8 + k8) * KBLK
                                          + grp * 8 + qd * 2);
                uint32_t bf[2] = {p.x, p.y};
                mma_tf32(sacc[0][nt], af[0], bf);
                mma_tf32(sacc[1][nt], af[1], bf);
            }
        }

#pragma unroll
        for (int mt = 0; mt < 2; mt++) {
            int r0 = wm * 32 + mt * 16 + grp;
            float il0 = St[h * 128 + r0];
            float il1 = St[h * 128 + r0 + 8];
#pragma unroll
            for (int nt = 0; nt < 4; nt++) {
                aacc[mt][nt][0] += ex2(sacc[mt][nt][0] * C2) * il0;
                aacc[mt][nt][1] += ex2(sacc[mt][nt][1] * C2) * il0;
                aacc[mt][nt][2] += ex2(sacc[mt][nt][2] * C2) * il1;
                aacc[mt][nt][3] += ex2(sacc[mt][nt][3] * C2) * il1;
            }
        }
    }

    const float inv8 = 1.0f / NH;
#pragma unroll
    for (int mt = 0; mt < 2; mt++) {
        int qrow = qt * 128 + wm * 32 + mt * 16 + grp;
        int kcol = kc * 64 + wn * 32;
        float* A0 = avg + ((size_t)(b * TT) + qrow) * TT + kcol;
        float* A1 = A0 + (size_t)8 * TT;
#pragma unroll
        for (int nt = 0; nt < 4; nt++) {
            *(float2*)(A0 + nt * 8 + qd * 2) =
                make_float2(aacc[mt][nt][0] * inv8, aacc[mt][nt][1] * inv8);
            *(float2*)(A1 + nt * 8 + qd * 2) =
                make_float2(aacc[mt][nt][2] * inv8, aacc[mt][nt][3] * inv8);
        }
    }
}

// ---------------- embedding + positional ------------------------------------
__global__ void embed_kernel(const int* __restrict__ x,
                             const float* __restrict__ emb,
                             const float* __restrict__ pos,
                             float* __restrict__ out) {
    int idx = blockIdx.x * blockDim.x + threadIdx.x;
    if (idx >= MT * CC) return;
    int c  = idx % CC;
    int bt = idx / CC;
    int t  = bt % TT;
    int tok = x[bt];
    if (tok < 0) tok = 0;
    if (tok >= VOCAB) tok = VOCAB - 1;
    out[idx] = emb[(size_t)tok * CC + c] + pos[(size_t)t * CC + c];
}

// ---------------- layernorm: one warp per 512-float row ----------------------
template<int RND>
__global__ void ln_kernel(const float* __restrict__ in,
                          const float* __restrict__ g,
                          const float* __restrict__ b,
                          float* __restrict__ out) {
    int row  = blockIdx.x * 8 + (threadIdx.x >> 5);
    int lane = threadIdx.x & 31;
    const float4* xr = (const float4*)(in + (size_t)row * CC);
    float4 v[4];
    float s = 0.f;
#pragma unroll
    for (int i = 0; i < 4; i++) {
        v[i] = xr[i * 32 + lane];
        s += v[i].x + v[i].y + v[i].z + v[i].w;
    }
#pragma unroll
    for (int o = 16; o; o >>= 1) s += __shfl_xor_sync(0xffffffffu, s, o);
    float mean = s * (1.0f / CC);
    float var = 0.f;
#pragma unroll
    for (int i = 0; i < 4; i++) {
        float dx = v[i].x - mean, dy = v[i].y - mean, dz = v[i].z - mean, dw = v[i].w - mean;
        var += dx * dx + dy * dy + dz * dz + dw * dw;
    }
#pragma unroll
    for (int o = 16; o; o >>= 1) var += __shfl_xor_sync(0xffffffffu, var, o);
    float rstd = rsqrtf(var * (1.0f / CC) + 1e-5f);
    float4* op = (float4*)(out + (size_t)row * CC);
    const float4* gp = (const float4*)g;
    const float4* bp = (const float4*)b;
#pragma unroll
    for (int i = 0; i < 4; i++) {
        float4 gg = gp[i * 32 + lane], bb = bp[i * 32 + lane];
        float4 o4;
        o4.x = (v[i].x - mean) * rstd * gg.x + bb.x;
        o4.y = (v[i].y - mean) * rstd * gg.y + bb.y;
        o4.z = (v[i].z - mean) * rstd * gg.z + bb.z;
        o4.w = (v[i].w - mean) * rstd * gg.w + bb.w;
        if (RND) {
            o4.x = rnd_tf32(o4.x); o4.y = rnd_tf32(o4.y);
            o4.z = rnd_tf32(o4.z); o4.w = rnd_tf32(o4.w);
        }
        op[i * 32 + lane] = o4;
    }
}

// ---------------- final pooled output: mean over T of lnf(x) ----------------
__global__ void final_mean_kernel(const float* __restrict__ hln,
                                  float* __restrict__ out) {
    int bd = blockIdx.x;
    int b = bd / CC, d = bd % CC;
    __shared__ float red[256];
    int tid = threadIdx.x;
    float s = 0.f;
    for (int t = tid; t < TT; t += 256)
        s += hln[((size_t)b * TT + t) * CC + d];
    red[tid] = s; __syncthreads();
    for (int o = 128; o > 0; o >>= 1) { if (tid < o) red[tid] += red[tid + o]; __syncthreads(); }
    if (tid == 0) out[bd] = red[0] * (1.0f / TT);
}

// ---------------- launch ------------------------------------------------------
extern "C" void kernel_launch(void* const* d_in, const int* in_sizes, int n_in,
                              void* d_out, int out_size) {
    const int* x      = (const int*)d_in[0];
    const float* emb  = (const float*)d_in[1];
    const float* pos  = (const float*)d_in[2];
    const float* Wq = (const float*)d_in[3],  *bq = (const float*)d_in[4];
    const float* Wk = (const float*)d_in[5],  *bk = (const float*)d_in[6];
    const float* Wv = (const float*)d_in[7],  *bv = (const float*)d_in[8];
    const float* Wo = (const float*)d_in[9],  *bo = (const float*)d_in[10];
    const float* W1 = (const float*)d_in[11], *b1 = (const float*)d_in[12];
    const float* W2 = (const float*)d_in[13], *b2 = (const float*)d_in[14];
    const float* ln1g = (const float*)d_in[15], *ln1b = (const float*)d_in[16];
    const float* ln2g = (const float*)d_in[17], *ln2b = (const float*)d_in[18];
    const float* lnfg = (const float*)d_in[19], *lnfb = (const float*)d_in[20];
    float* out = (float*)d_out;

    float *xb, *lnb, *qb, *kb, *vb, *ab, *fb, *wp;
    cudaGetSymbolAddress((void**)&xb,  g_x);
    cudaGetSymbolAddress((void**)&lnb, g_ln);
    cudaGetSymbolAddress((void**)&qb,  g_q);
    cudaGetSymbolAddress((void**)&kb,  g_k);
    cudaGetSymbolAddress((void**)&vb,  g_v);
    cudaGetSymbolAddress((void**)&ab,  g_attn);
    cudaGetSymbolAddress((void**)&fb,  g_ff);
    cudaGetSymbolAddress((void**)&wp,  g_wpack);

    const float* pWq = wp;
    const float* pWk = wp + (size_t)WSEG_P;
    const float* pWv = wp + (size_t)2 * WSEG_P;
    const float* pWo = wp + (size_t)3 * WSEG_P;
    const float* pW1 = wp + (size_t)4 * WSEG_P;
    const float* pW2 = wp + (size_t)4 * WSEG_P + WSEG_F;

    const int SM_128_128 = 3 * (128 * 36 + 128 * 36) * 4;               // 110592
    const int SM_64_128  = 3 * (64 * 36 + 128 * 36) * 4;                // 82944
    const int SM_FLASH   = (2 * 32 * 68 + 2 * 64 * 56) * 4;             // 46080
    const int SM_AVG     = (64 * 132 + 64 * 68) * 4 + NH * 128 * 4;     // 55296

    cudaFuncSetAttribute((const void*)gemm_qkv_kernel<128, 128>,
                         cudaFuncAttributeMaxDynamicSharedMemorySize, SM_128_128);
    cudaFuncSetAttribute((const void*)gemm_tc_kernel<2, 128, 128>,
                         cudaFuncAttributeMaxDynamicSharedMemorySize, SM_128_128);
    cudaFuncSetAttribute((const void*)gemm_tc_kernel<3, 64, 128>,
                         cudaFuncAttributeMaxDynamicSharedMemorySize, SM_64_128);
    cudaFuncSetAttribute((const void*)flash_kernel,
                         cudaFuncAttributeMaxDynamicSharedMemorySize, SM_FLASH);
    cudaFuncSetAttribute((const void*)avgmap_kernel,
                         cudaFuncAttributeMaxDynamicSharedMemorySize, SM_AVG);

    const size_t attn_elems = (size_t)NLAYER * BB * TT * TT;
    float* attn_out = out + ((size_t)out_size - attn_elems);

    {
        dim3 gw(WSEG_F / 4 / 256, 6);
        round_weights_kernel<<<gw, 256>>>(Wq, Wk, Wv, Wo, W1, W2, wp);
    }

    embed_kernel<<<(MT * CC + 255) / 256, 256>>>(x, emb, pos, xb);

    for (int l = 0; l < NLAYER; l++) {
        const float* wq = pWq + (size_t)l * CC * CC;
        const float* wk = pWk + (size_t)l * CC * CC;
        const float* wv = pWv + (size_t)l * CC * CC;
        const float* wo = pWo + (size_t)l * CC * CC;
        const float* w1 = pW1 + (size_t)l * FF * CC;
        const float* w2 = pW2 + (size_t)l * CC * FF;

        ln_kernel<1><<<MT / 8, 256>>>(xb, ln1g + (size_t)l * CC, ln1b + (size_t)l * CC, lnb);

        dim3 gqkv(CC / 128, MT / 128, 3);
        gemm_qkv_kernel<128, 128><<<gqkv, 256, SM_128_128>>>(
            lnb, wq, wk, wv,
            bq + (size_t)l * CC, bk + (size_t)l * CC, bv + (size_t)l * CC,
            qb, kb, vb);

        // fused flash attention: O + inv-l (main stream)
        dim3 gfl(TT / 128, NH, BB);
        flash_kernel<<<gfl, 256, SM_FLASH>>>(qb, kb, vb, ab);

        // fork: head-averaged attention map on side stream
        cudaEventRecord(g_si.evF[l], 0);
        cudaStreamWaitEvent(g_si.s2, g_si.evF[l], 0);
        dim3 gav(TT / 64, TT / 128, BB);
        avgmap_kernel<<<gav, 256, SM_AVG, g_si.s2>>>(
            qb, kb, attn_out + (size_t)l * BB * TT * TT);
        cudaEventRecord(g_si.evA[l], g_si.s2);

        // main stream continues: Wo projection + residual
        dim3 gwo(CC / 128, MT / 64, 1);
        gemm_tc_kernel<3, 64, 128><<<gwo, 256, SM_64_128>>>(
            ab, wo, bo + (size_t)l * CC, xb, xb, CC, CC, CC, CC);

        ln_kernel<1><<<MT / 8, 256>>>(xb, ln2g + (size_t)l * CC, ln2b + (size_t)l * CC, lnb);

        dim3 gf1(FF / 128, MT / 128, 1);
        gemm_tc_kernel<2, 128, 128><<<gf1, 256, SM_128_128>>>(
            lnb, w1, b1 + (size_t)l * FF, nullptr, fb, CC, CC, FF, CC);

        dim3 gf2(CC / 128, MT / 64, 1);
        gemm_tc_kernel<3, 64, 128><<<gf2, 256, SM_64_128>>>(
            fb, w2, b2 + (size_t)l * CC, xb, xb, FF, FF, CC, FF);

        // join: next layer's QKV overwrites q/k which avgmap reads
        cudaStreamWaitEvent(0, g_si.evA[l], 0);
    }

    ln_kernel<0><<<MT / 8, 256>>>(xb, lnfg, lnfb, lnb);
    final_mean_kernel<<<BB * CC, 256>>>(lnb, out);
}

// round 16
// speedup vs baseline: 1.0382x; 1.0061x over previous
#include <cuda_runtime.h>
#include <math.h>
#include <stdint.h>

#define NLAYER 4
#define BB 2
#define TT 2048
#define CC 512
#define NH 8
#define HDIM 64
#define FF 2048
#define VOCAB 32000
#define MT (BB*TT)   // 4096 rows

// ---------------- scratch (device globals; no allocations allowed) ----------
__device__ float g_x   [(size_t)MT*CC];
__device__ float g_ln  [(size_t)MT*CC];
__device__ float g_q   [(size_t)MT*CC];
__device__ float g_k   [(size_t)MT*CC];
__device__ float g_v   [(size_t)MT*CC];
__device__ float g_attn[(size_t)MT*CC];
__device__ float g_ff  [(size_t)MT*FF];
__device__ float g_linv[(size_t)BB*NH*TT];   // per-row 1/l from flash pass

// pre-rounded (tf32) weight copies: [Wq][Wk][Wv][Wo][W1][W2], each all-layers
#define WSEG_P (NLAYER*CC*CC)      // 1048576 (projection matrices)
#define WSEG_F (NLAYER*FF*CC)      // 4194304 (FFN matrices)
__device__ float g_wpack[(size_t)4*WSEG_P + 2*WSEG_F];   // ~50 MB

// ---------------- side stream + events (created at static init, reused) -----
struct StreamInit {
    cudaStream_t s2;
    cudaEvent_t evF[NLAYER], evA[NLAYER];
    StreamInit() {
        cudaStreamCreateWithFlags(&s2, cudaStreamNonBlocking);
        for (int i = 0; i < NLAYER; i++) {
            cudaEventCreateWithFlags(&evF[i], cudaEventDisableTiming);
            cudaEventCreateWithFlags(&evA[i], cudaEventDisableTiming);
        }
    }
};
static StreamInit g_si;

// ---------------- helpers ----------------------------------------------------
__device__ __forceinline__ uint32_t f2tf32(float x) {
    uint32_t u;
    asm("cvt.rna.tf32.f32 %0, %1;" : "=r"(u) : "f"(x));
    return u;
}
__device__ __forceinline__ float rnd_tf32(float x) {
    return __uint_as_float(f2tf32(x));
}

__device__ __forceinline__ float ex2(float x) {
    float y;
    asm("ex2.approx.f32 %0, %1;" : "=f"(y) : "f"(x));
    return y;
}

__device__ __forceinline__ void mma_tf32(float* c, const uint32_t* a, const uint32_t* b) {
    asm volatile(
        "mma.sync.aligned.m16n8k8.row.col.f32.tf32.tf32.f32 "
        "{%0,%1,%2,%3}, {%4,%5,%6,%7}, {%8,%9}, {%0,%1,%2,%3};"
        : "+f"(c[0]), "+f"(c[1]), "+f"(c[2]), "+f"(c[3])
        : "r"(a[0]), "r"(a[1]), "r"(a[2]), "r"(a[3]), "r"(b[0]), "r"(b[1]));
}

__device__ __forceinline__ void cp16(void* sdst, const void* gsrc) {
    unsigned s = (unsigned)__cvta_generic_to_shared(sdst);
    asm volatile("cp.async.cg.shared.global [%0], [%1], 16;\n" :: "r"(s), "l"(gsrc));
}
__device__ __forceinline__ void cp_commit() { asm volatile("cp.async.commit_group;\n"); }
template<int N>
__device__ __forceinline__ void cp_wait() { asm volatile("cp.async.wait_group %0;\n" :: "n"(N)); }

// ---------------- weight pre-rounding (runs once per launch) -----------------
__global__ void round_weights_kernel(const float* __restrict__ wq,
                                     const float* __restrict__ wk,
                                     const float* __restrict__ wv,
                                     const float* __restrict__ wo,
                                     const float* __restrict__ w1,
                                     const float* __restrict__ w2,
                                     float* __restrict__ dst) {
    const int seg = blockIdx.y;
    const float* src;
    size_t off, n;
    switch (seg) {
        case 0: src = wq; off = 0;                          n = WSEG_P; break;
        case 1: src = wk; off = (size_t)WSEG_P;             n = WSEG_P; break;
        case 2: src = wv; off = (size_t)2 * WSEG_P;         n = WSEG_P; break;
        case 3: src = wo; off = (size_t)3 * WSEG_P;         n = WSEG_P; break;
        case 4: src = w1; off = (size_t)4 * WSEG_P;         n = WSEG_F; break;
        default: src = w2; off = (size_t)4 * WSEG_P + WSEG_F; n = WSEG_F; break;
    }
    size_t i4 = (size_t)blockIdx.x * blockDim.x + threadIdx.x;
    if (i4 * 4 >= n) return;
    float4 t = ((const float4*)src)[i4];
    t.x = rnd_tf32(t.x); t.y = rnd_tf32(t.y);
    t.z = rnd_tf32(t.z); t.w = rnd_tf32(t.w);
    ((float4*)(dst + off))[i4] = t;
}

// =============================================================================
// TF32 tensor-core GEMM core (NT). C[M,N] = A[M,K] @ W[N,K]^T
// Pre-rounded operands; 3-stage cp.async pipeline, one sync per chunk.
// EPI: 1 = +bias, 2 = +bias,relu (tf32-rounded output), 3 = +bias,+residual
// =============================================================================
template<int EPI, int BM, int BN>
__device__ __forceinline__ void gemm_core(
    const float* __restrict__ A, const float* __restrict__ B,
    const float* __restrict__ bias, const float* __restrict__ res,
    float* __restrict__ C, int lda, int ldb, int ldc, int K)
{
    constexpr int WM   = BM / 64;
    constexpr int WN   = 8 / WM;
    constexpr int NCW  = BN / WN;
    constexpr int NT_  = NCW / 8;
    constexpr int ASZ  = BM * 36;
    constexpr int BSZ  = BN * 36;

    extern __shared__ float smem[];
    float* As = smem;                        // 3 * ASZ
    float* Bs = smem + 3 * ASZ;              // 3 * BSZ

    const int tid  = threadIdx.x;
    const int lane = tid & 31, wid = tid >> 5;
    const int warpM = (WM == 1) ? 0 : (wid & 1);
    const int warpN = (WM == 1) ? wid : (wid >> 1);
    const int grp = lane >> 2, qd = lane & 3;

    const int row0 = blockIdx.y * BM;
    const int col0 = blockIdx.x * BN;

    float acc[4][NT_][4];
#pragma unroll
    for (int mt = 0; mt < 4; mt++)
#pragma unroll
        for (int nt = 0; nt < NT_; nt++)
#pragma unroll
            for (int i = 0; i < 4; i++) acc[mt][nt][i] = 0.f;

    auto loadA = [&](int buf, int k0) {
#pragma unroll
        for (int i = 0; i < BM / 32; i++) {
            int idx = i * 256 + tid;
            int r = idx >> 3, c4 = (idx & 7) << 2;
            cp16(As + buf * ASZ + r * 36 + c4,
                 A + (size_t)(row0 + r) * lda + k0 + c4);
        }
    };
    auto loadB = [&](int buf, int k0) {
#pragma unroll
        for (int i = 0; i < BN / 32; i++) {
            int idx = i * 256 + tid;
            int r = idx >> 3, c4 = (idx & 7) << 2;
            cp16(Bs + buf * BSZ + r * 36 + c4,
                 B + (size_t)(col0 + r) * ldb + k0 + c4);
        }
    };

    auto compute = [&](int buf) {
        const float* Ab = As + buf * ASZ;
        const float* Bb = Bs + buf * BSZ;
#pragma unroll
        for (int kt = 0; kt < 4; kt++) {
            uint32_t af[4][4];
#pragma unroll
            for (int mt = 0; mt < 4; mt++) {
                int r0 = warpM * 64 + mt * 16 + grp;
                af[mt][0] = __float_as_uint(Ab[(r0)     * 36 + kt * 8 + qd]);
                af[mt][1] = __float_as_uint(Ab[(r0 + 8) * 36 + kt * 8 + qd]);
                af[mt][2] = __float_as_uint(Ab[(r0)     * 36 + kt * 8 + qd + 4]);
                af[mt][3] = __float_as_uint(Ab[(r0 + 8) * 36 + kt * 8 + qd + 4]);
            }
            uint32_t bf[NT_][2];
#pragma unroll
            for (int nt = 0; nt < NT_; nt++) {
                int nb = warpN * NCW + nt * 8 + grp;
                bf[nt][0] = __float_as_uint(Bb[nb * 36 + kt * 8 + qd]);
                bf[nt][1] = __float_as_uint(Bb[nb * 36 + kt * 8 + qd + 4]);
            }
#pragma unroll
            for (int mt = 0; mt < 4; mt++)
#pragma unroll
                for (int nt = 0; nt < NT_; nt++)
                    mma_tf32(acc[mt][nt], af[mt], bf[nt]);
        }
    };

    const int nk = K >> 5;
    loadA(0, 0);  loadB(0, 0);  cp_commit();
    loadA(1, 32); loadB(1, 32); cp_commit();

    int buf = 0;
    int nbuf = 2;
    for (int kb = 0; kb < nk; kb++) {
        cp_wait<1>();
        __syncthreads();
        int nb = kb + 2;
        if (nb < nk) { loadA(nbuf, nb * 32); loadB(nbuf, nb * 32); }
        cp_commit();
        compute(buf);
        buf = (buf == 2) ? 0 : buf + 1;
        nbuf = (nbuf == 2) ? 0 : nbuf + 1;
    }

#pragma unroll
    for (int mt = 0; mt < 4; mt++)
#pragma unroll
        for (int nt = 0; nt < NT_; nt++) {
            int row = row0 + warpM * 64 + mt * 16 + grp;
            int col = col0 + warpN * NCW + nt * 8 + qd * 2;
#pragma unroll
            for (int half = 0; half < 2; half++) {
                int r = row + half * 8;
                float v0 = acc[mt][nt][half * 2 + 0];
                float v1 = acc[mt][nt][half * 2 + 1];
                v0 += bias[col]; v1 += bias[col + 1];
                if (EPI == 2) {
                    v0 = rnd_tf32(fmaxf(v0, 0.f));
                    v1 = rnd_tf32(fmaxf(v1, 0.f));
                }
                if (EPI == 3) {
                    v0 += res[(size_t)r * ldc + col];
                    v1 += res[(size_t)r * ldc + col + 1];
                }
                *(float2*)(C + (size_t)r * ldc + col) = make_float2(v0, v1);
            }
        }
}

template<int EPI, int BM, int BN>
__global__ void __launch_bounds__(256, 2)
gemm_tc_kernel(const float* __restrict__ A, const float* __restrict__ B,
               const float* __restrict__ bias, const float* __restrict__ res,
               float* __restrict__ C, int lda, int ldb, int ldc, int K) {
    gemm_core<EPI, BM, BN>(A, B, bias, res, C, lda, ldb, ldc, K);
}

// ---- fused QKV (z selects weight/bias/output); BN=128 (validated) -----------
template<int BM, int BN>
__global__ void __launch_bounds__(256, 2)
gemm_qkv_kernel(const float* __restrict__ A,
                const float* __restrict__ Wq, const float* __restrict__ Wk,
                const float* __restrict__ Wv,
                const float* __restrict__ bq, const float* __restrict__ bk,
                const float* __restrict__ bv,
                float* __restrict__ q, float* __restrict__ k, float* __restrict__ v) {
    int z = blockIdx.z;
    const float* B    = z == 0 ? Wq : (z == 1 ? Wk : Wv);
    const float* bias = z == 0 ? bq : (z == 1 ? bk : bv);
    float* C          = z == 0 ? q  : (z == 1 ? k  : v);
    gemm_core<1, BM, BN>(A, B, bias, nullptr, C, CC, CC, CC, CC);
}

// =============================================================================
// Flash attention pass 1 (validated R13/R14: max-free softmax, transposed V).
// =============================================================================
__global__ void __launch_bounds__(256, 2)
flash_kernel(const float* __restrict__ q, const float* __restrict__ k,
             const float* __restrict__ v, float* __restrict__ o) {
    constexpr int KT = 32, NKT = TT / KT;
    constexpr int KBLK = 68;
    constexpr int PVT = 56;
    const float SCALEQ = 0.125f * 1.44269504089f;
    extern __shared__ uint32_t usm[];
    uint32_t* Kf = usm;                     // 2 * 32 * 68
    uint32_t* Vt = usm + 2 * 32 * KBLK;     // 2 * 64 * 56

    const int qt = blockIdx.x, h = blockIdx.y, b = blockIdx.z;
    const int tid = threadIdx.x, lane = tid & 31, w = tid >> 5;
    const int grp = lane >> 2, qd = lane & 3;
    const int rbase = w * 16;

    const float* Qp = q + ((size_t)(b * TT) + qt * 128) * CC + h * 64;
    const float* Kp = k + (size_t)b * TT * CC + h * 64;
    const float* Vp = v + (size_t)b * TT * CC + h * 64;

    uint32_t qf[8][4];
#pragma unroll
    for (int k8 = 0; k8 < 8; k8++) {
        const float* Qr0 = Qp + (size_t)(rbase + grp) * CC + k8 * 8 + qd;
        const float* Qr1 = Qr0 + (size_t)8 * CC;
        qf[k8][0] = f2tf32(Qr0[0] * SCALEQ);
        qf[k8][1] = f2tf32(Qr1[0] * SCALEQ);
        qf[k8][2] = f2tf32(Qr0[4] * SCALEQ);
        qf[k8][3] = f2tf32(Qr1[4] * SCALEQ);
    }

    const int skr = tid >> 3, skc = (tid & 7) * 8;
    const int vc = tid & 63, vrb = (tid >> 6) * 8;

    float4 kr0, kr1;
    float vreg[8];
    auto ldgKV = [&](int kt) {
        const float* Kt = Kp + (size_t)(kt * KT + skr) * CC + skc;
        kr0 = *(const float4*)(Kt);
        kr1 = *(const float4*)(Kt + 4);
        const float* Vtg = Vp + (size_t)(kt * KT + vrb) * CC + vc;
#pragma unroll
        for (int i = 0; i < 8; i++) vreg[i] = Vtg[(size_t)i * CC];
    };
    auto stsKV = [&](int buf) {
        uint32_t* kd = Kf + buf * 32 * KBLK
                     + ((skr >> 3) * 8 + (skc >> 3)) * KBLK + (skr & 7) * 8;
        uint4 ua, ub;
        ua.x = f2tf32(kr0.x); ua.y = f2tf32(kr1.x); ua.z = f2tf32(kr0.y); ua.w = f2tf32(kr1.y);
        ub.x = f2tf32(kr0.z); ub.y = f2tf32(kr1.z); ub.z = f2tf32(kr0.w); ub.w = f2tf32(kr1.w);
        *(uint4*)(kd)     = ua;
        *(uint4*)(kd + 4) = ub;
        uint32_t* vd = Vt + buf * 64 * PVT + vc * PVT + vrb;
        uint4 u0, u1;
        u0.x = f2tf32(vreg[0]); u0.y = f2tf32(vreg[1]);
        u0.z = f2tf32(vreg[2]); u0.w = f2tf32(vreg[3]);
        u1.x = f2tf32(vreg[4]); u1.y = f2tf32(vreg[5]);
        u1.z = f2tf32(vreg[6]); u1.w = f2tf32(vreg[7]);
        *(uint4*)(vd)     = u0;
        *(uint4*)(vd + 4) = u1;
    };

    float oacc[8][4];
#pragma unroll
    for (int nt = 0; nt < 8; nt++)
#pragma unroll
        for (int i = 0; i < 4; i++) oacc[nt][i] = 0.f;
    float l0 = 0.f, l1 = 0.f;

    ldgKV(0);
    stsKV(0);
    __syncthreads();

    for (int kt = 0; kt < NKT; kt++) {
        const int buf = kt & 1;
        if (kt + 1 < NKT) ldgKV(kt + 1);

        const uint32_t* Kb = Kf + buf * 32 * KBLK;
        const uint32_t* Vb = Vt + buf * 64 * PVT;

        float sacc[4][4];
#pragma unroll
        for (int nt = 0; nt < 4; nt++)
#pragma unroll
            for (int i = 0; i < 4; i++) sacc[nt][i] = 0.f;
#pragma unroll
        for (int k8 = 0; k8 < 8; k8++) {
#pragma unroll
            for (int nt = 0; nt < 4; nt++) {
                uint2 p = *(const uint2*)(Kb + (nt * 8 + k8) * KBLK + grp * 8 + qd * 2);
                uint32_t bf[2] = {p.x, p.y};
                mma_tf32(sacc[nt], qf[k8], bf);
            }
        }

        float rs0 = 0.f, rs1 = 0.f;
#pragma unroll
        for (int nt = 0; nt < 4; nt++) {
            sacc[nt][0] = ex2(sacc[nt][0]);
            sacc[nt][1] = ex2(sacc[nt][1]);
            sacc[nt][2] = ex2(sacc[nt][2]);
            sacc[nt][3] = ex2(sacc[nt][3]);
            rs0 += sacc[nt][0] + sacc[nt][1];
            rs1 += sacc[nt][2] + sacc[nt][3];
        }
        rs0 += __shfl_xor_sync(0xffffffffu, rs0, 1);
        rs0 += __shfl_xor_sync(0xffffffffu, rs0, 2);
        rs1 += __shfl_xor_sync(0xffffffffu, rs1, 1);
        rs1 += __shfl_xor_sync(0xffffffffu, rs1, 2);
        l0 += rs0;
        l1 += rs1;

#pragma unroll
        for (int kb = 0; kb < 4; kb++) {
            uint32_t af[4];
            af[0] = f2tf32(sacc[kb][0]);
            af[1] = f2tf32(sacc[kb][2]);
            af[2] = f2tf32(sacc[kb][1]);
            af[3] = f2tf32(sacc[kb][3]);
#pragma unroll
            for (int nt = 0; nt < 8; nt++) {
                uint2 p = *(const uint2*)(Vb + (nt * 8 + grp) * PVT + kb * 8 + 2 * qd);
                uint32_t bf[2] = {p.x, p.y};
                mma_tf32(oacc[nt], af, bf);
            }
        }

        if (kt + 1 < NKT) stsKV(buf ^ 1);
        __syncthreads();
    }

    float i0 = 1.f / l0, i1 = 1.f / l1;
    int row0 = qt * 128 + rbase + grp;
    float* Op = o + ((size_t)(b * TT) + row0) * CC + h * 64;
#pragma unroll
    for (int nt = 0; nt < 8; nt++) {
        *(float2*)(Op + nt * 8 + qd * 2) =
            make_float2(rnd_tf32(oacc[nt][0] * i0), rnd_tf32(oacc[nt][1] * i0));
        *(float2*)(Op + (size_t)8 * CC + nt * 8 + qd * 2) =
            make_float2(rnd_tf32(oacc[nt][2] * i1), rnd_tf32(oacc[nt][3] * i1));
    }
    if (qd == 0) {
        g_linv[(size_t)(b * NH + h) * TT + row0]     = i0;
        g_linv[(size_t)(b * NH + h) * TT + row0 + 8] = i1;
    }
}

// =============================================================================
// Pass 2: head-averaged attention map. Each CTA now covers TWO 64-col chunks
// (outer kcc loop over the validated R11 body) -> grid 512 instead of 1024:
// 1.73 waves instead of 3.46 at 2 CTAs/SM. Stats staged once per CTA.
// =============================================================================
__global__ void __launch_bounds__(256, 2)
avgmap_kernel(const float* __restrict__ q, const float* __restrict__ k,
              float* __restrict__ avg) {
    constexpr int QBLK = 132, KBLK = 68;
    const float C2 = 0.125f * 1.44269504089f;
    extern __shared__ uint32_t usm[];
    uint32_t* QF = usm;
    uint32_t* KF = usm + 64 * QBLK;
    float* St = (float*)(usm + 64 * QBLK + 64 * KBLK);   // [8][128] inv-l

    const int kc2 = blockIdx.x, qt = blockIdx.y, b = blockIdx.z;
    const int tid = threadIdx.x, lane = tid & 31, w = tid >> 5;
    const int grp = lane >> 2, qd = lane & 3;
    const int wm = w >> 1, wn = w & 1;

    for (int j = tid; j < NH * 128; j += 256)
        St[j] = g_linv[(size_t)(b * NH + (j >> 7)) * TT + qt * 128 + (j & 127)];

    const int kkr = tid >> 2, kc0 = (tid & 3) * 16;
    float4 kreg[4];

    for (int kcc = 0; kcc < 2; kcc++) {
        const int kc = kc2 * 2 + kcc;

        auto ldgK = [&](int h) {
            const float* Kp = k + ((size_t)(b * TT) + kc * 64 + kkr) * CC + h * 64 + kc0;
#pragma unroll
            for (int i = 0; i < 4; i++) kreg[i] = *(const float4*)(Kp + i * 4);
        };

        float aacc[2][4][4];
#pragma unroll
        for (int mt = 0; mt < 2; mt++)
#pragma unroll
            for (int nt = 0; nt < 4; nt++)
#pragma unroll
                for (int i = 0; i < 4; i++) aacc[mt][nt][i] = 0.f;

        ldgK(0);

        for (int h = 0; h < NH; h++) {
            __syncthreads();   // buffers free (prev compute done; covers kcc loop)
            {
                uint32_t* kb0 = KF + ((kkr >> 3) * 8 + (kc0 >> 3)) * KBLK + (kkr & 7) * 8;
#pragma unroll
                for (int bb = 0; bb < 2; bb++) {
                    float4 f0 = kreg[bb * 2], f1 = kreg[bb * 2 + 1];
                    uint4 ua, ub;
                    ua.x = f2tf32(f0.x); ua.y = f2tf32(f1.x); ua.z = f2tf32(f0.y); ua.w = f2tf32(f1.y);
                    ub.x = f2tf32(f0.z); ub.y = f2tf32(f1.z); ub.z = f2tf32(f0.w); ub.w = f2tf32(f1.w);
                    *(uint4*)(kb0 + bb * KBLK)     = ua;
                    *(uint4*)(kb0 + bb * KBLK + 4) = ub;
                }
            }
            {
                const float* Qp = q + ((size_t)(b * TT) + qt * 128) * CC + h * 64;
#pragma unroll
                for (int i = 0; i < 8; i++) {
                    int j = i * 256 + tid;
                    int r = j >> 4, c4 = (j & 15) << 2;
                    float4 t4 = *(const float4*)(Qp + (size_t)r * CC + c4);
                    int blk  = (r >> 4) * 8 + (c4 >> 3);
                    int base = blk * QBLK + ((c4 >> 2) & 1) * 2 + ((r >> 3) & 1);
                    int ro   = (r & 7) * 4;
                    QF[base + (ro + 0) * 4] = f2tf32(t4.x);
                    QF[base + (ro + 1) * 4] = f2tf32(t4.y);
                    QF[base + (ro + 2) * 4] = f2tf32(t4.z);
                    QF[base + (ro + 3) * 4] = f2tf32(t4.w);
                }
            }
            if (h + 1 < NH) ldgK(h + 1);
            __syncthreads();

            float sacc[2][4][4];
#pragma unroll
            for (int mt = 0; mt < 2; mt++)
#pragma unroll
                for (int nt = 0; nt < 4; nt++)
#pragma unroll
                    for (int i = 0; i < 4; i++) sacc[mt][nt][i] = 0.f;

#pragma unroll
            for (int k8 = 0; k8 < 8; k8++) {
                uint32_t af[2][4];
#pragma unroll
                for (int mt = 0; mt < 2; mt++) {
                    uint4 u = *(const uint4*)(QF + ((wm * 2 + mt) * 8 + k8) * QBLK
                                              + (grp * 4 + qd) * 4);
                    af[mt][0] = u.x; af[mt][1] = u.y; af[mt][2] = u.z; af[mt][3] = u.w;
                }
#pragma unroll
                for (int nt = 0; nt < 4; nt++) {
                    uint2 p = *(const uint2*)(KF + ((wn * 4 + nt) * 8 + k8) * KBLK
                                              + grp * 8 + qd * 2);
                    uint32_t bf[2] = {p.x, p.y};
                    mma_tf32(sacc[0][nt], af[0], bf);
                    mma_tf32(sacc[1][nt], af[1], bf);
                }
            }

#pragma unroll
            for (int mt = 0; mt < 2; mt++) {
                int r0 = wm * 32 + mt * 16 + grp;
                float il0 = St[h * 128 + r0];
                float il1 = St[h * 128 + r0 + 8];
#pragma unroll
                for (int nt = 0; nt < 4; nt++) {
                    aacc[mt][nt][0] += ex2(sacc[mt][nt][0] * C2) * il0;
                    aacc[mt][nt][1] += ex2(sacc[mt][nt][1] * C2) * il0;
                    aacc[mt][nt][2] += ex2(sacc[mt][nt][2] * C2) * il1;
                    aacc[mt][nt][3] += ex2(sacc[mt][nt][3] * C2) * il1;
                }
            }
        }

        const float inv8 = 1.0f / NH;
#pragma unroll
        for (int mt = 0; mt < 2; mt++) {
            int qrow = qt * 128 + wm * 32 + mt * 16 + grp;
            int kcol = kc * 64 + wn * 32;
            float* A0 = avg + ((size_t)(b * TT) + qrow) * TT + kcol;
            float* A1 = A0 + (size_t)8 * TT;
#pragma unroll
            for (int nt = 0; nt < 4; nt++) {
                *(float2*)(A0 + nt * 8 + qd * 2) =
                    make_float2(aacc[mt][nt][0] * inv8, aacc[mt][nt][1] * inv8);
                *(float2*)(A1 + nt * 8 + qd * 2) =
                    make_float2(aacc[mt][nt][2] * inv8, aacc[mt][nt][3] * inv8);
            }
        }
    }
}

// ---------------- embedding + positional ------------------------------------
__global__ void embed_kernel(const int* __restrict__ x,
                             const float* __restrict__ emb,
                             const float* __restrict__ pos,
                             float* __restrict__ out) {
    int idx = blockIdx.x * blockDim.x + threadIdx.x;
    if (idx >= MT * CC) return;
    int c  = idx % CC;
    int bt = idx / CC;
    int t  = bt % TT;
    int tok = x[bt];
    if (tok < 0) tok = 0;
    if (tok >= VOCAB) tok = VOCAB - 1;
    out[idx] = emb[(size_t)tok * CC + c] + pos[(size_t)t * CC + c];
}

// ---------------- layernorm: one warp per 512-float row ----------------------
template<int RND>
__global__ void ln_kernel(const float* __restrict__ in,
                          const float* __restrict__ g,
                          const float* __restrict__ b,
                          float* __restrict__ out) {
    int row  = blockIdx.x * 8 + (threadIdx.x >> 5);
    int lane = threadIdx.x & 31;
    const float4* xr = (const float4*)(in + (size_t)row * CC);
    float4 v[4];
    float s = 0.f;
#pragma unroll
    for (int i = 0; i < 4; i++) {
        v[i] = xr[i * 32 + lane];
        s += v[i].x + v[i].y + v[i].z + v[i].w;
    }
#pragma unroll
    for (int o = 16; o; o >>= 1) s += __shfl_xor_sync(0xffffffffu, s, o);
    float mean = s * (1.0f / CC);
    float var = 0.f;
#pragma unroll
    for (int i = 0; i < 4; i++) {
        float dx = v[i].x - mean, dy = v[i].y - mean, dz = v[i].z - mean, dw = v[i].w - mean;
        var += dx * dx + dy * dy + dz * dz + dw * dw;
    }
#pragma unroll
    for (int o = 16; o; o >>= 1) var += __shfl_xor_sync(0xffffffffu, var, o);
    float rstd = rsqrtf(var * (1.0f / CC) + 1e-5f);
    float4* op = (float4*)(out + (size_t)row * CC);
    const float4* gp = (const float4*)g;
    const float4* bp = (const float4*)b;
#pragma unroll
    for (int i = 0; i < 4; i++) {
        float4 gg = gp[i * 32 + lane], bb = bp[i * 32 + lane];
        float4 o4;
        o4.x = (v[i].x - mean) * rstd * gg.x + bb.x;
        o4.y = (v[i].y - mean) * rstd * gg.y + bb.y;
        o4.z = (v[i].z - mean) * rstd * gg.z + bb.z;
        o4.w = (v[i].w - mean) * rstd * gg.w + bb.w;
        if (RND) {
            o4.x = rnd_tf32(o4.x); o4.y = rnd_tf32(o4.y);
            o4.z = rnd_tf32(o4.z); o4.w = rnd_tf32(o4.w);
        }
        op[i * 32 + lane] = o4;
    }
}

// ---------------- final pooled output: mean over T of lnf(x) ----------------
__global__ void final_mean_kernel(const float* __restrict__ hln,
                                  float* __restrict__ out) {
    int bd = blockIdx.x;
    int b = bd / CC, d = bd % CC;
    __shared__ float red[256];
    int tid = threadIdx.x;
    float s = 0.f;
    for (int t = tid; t < TT; t += 256)
        s += hln[((size_t)b * TT + t) * CC + d];
    red[tid] = s; __syncthreads();
    for (int o = 128; o > 0; o >>= 1) { if (tid < o) red[tid] += red[tid + o]; __syncthreads(); }
    if (tid == 0) out[bd] = red[0] * (1.0f / TT);
}

// ---------------- launch ------------------------------------------------------
extern "C" void kernel_launch(void* const* d_in, const int* in_sizes, int n_in,
                              void* d_out, int out_size) {
    const int* x      = (const int*)d_in[0];
    const float* emb  = (const float*)d_in[1];
    const float* pos  = (const float*)d_in[2];
    const float* Wq = (const float*)d_in[3],  *bq = (const float*)d_in[4];
    const float* Wk = (const float*)d_in[5],  *bk = (const float*)d_in[6];
    const float* Wv = (const float*)d_in[7],  *bv = (const float*)d_in[8];
    const float* Wo = (const float*)d_in[9],  *bo = (const float*)d_in[10];
    const float* W1 = (const float*)d_in[11], *b1 = (const float*)d_in[12];
    const float* W2 = (const float*)d_in[13], *b2 = (const float*)d_in[14];
    const float* ln1g = (const float*)d_in[15], *ln1b = (const float*)d_in[16];
    const float* ln2g = (const float*)d_in[17], *ln2b = (const float*)d_in[18];
    const float* lnfg = (const float*)d_in[19], *lnfb = (const float*)d_in[20];
    float* out = (float*)d_out;

    float *xb, *lnb, *qb, *kb, *vb, *ab, *fb, *wp;
    cudaGetSymbolAddress((void**)&xb,  g_x);
    cudaGetSymbolAddress((void**)&lnb, g_ln);
    cudaGetSymbolAddress((void**)&qb,  g_q);
    cudaGetSymbolAddress((void**)&kb,  g_k);
    cudaGetSymbolAddress((void**)&vb,  g_v);
    cudaGetSymbolAddress((void**)&ab,  g_attn);
    cudaGetSymbolAddress((void**)&fb,  g_ff);
    cudaGetSymbolAddress((void**)&wp,  g_wpack);

    const float* pWq = wp;
    const float* pWk = wp + (size_t)WSEG_P;
    const float* pWv = wp + (size_t)2 * WSEG_P;
    const float* pWo = wp + (size_t)3 * WSEG_P;
    const float* pW1 = wp + (size_t)4 * WSEG_P;
    const float* pW2 = wp + (size_t)4 * WSEG_P + WSEG_F;

    const int SM_128_128 = 3 * (128 * 36 + 128 * 36) * 4;               // 110592
    const int SM_64_128  = 3 * (64 * 36 + 128 * 36) * 4;                // 82944
    const int SM_FLASH   = (2 * 32 * 68 + 2 * 64 * 56) * 4;             // 46080
    const int SM_AVG     = (64 * 132 + 64 * 68) * 4 + NH * 128 * 4;     // 55296

    cudaFuncSetAttribute((const void*)gemm_qkv_kernel<128, 128>,
                         cudaFuncAttributeMaxDynamicSharedMemorySize, SM_128_128);
    cudaFuncSetAttribute((const void*)gemm_tc_kernel<2, 128, 128>,
                         cudaFuncAttributeMaxDynamicSharedMemorySize, SM_128_128);
    cudaFuncSetAttribute((const void*)gemm_tc_kernel<3, 64, 128>,
                         cudaFuncAttributeMaxDynamicSharedMemorySize, SM_64_128);
    cudaFuncSetAttribute((const void*)flash_kernel,
                         cudaFuncAttributeMaxDynamicSharedMemorySize, SM_FLASH);
    cudaFuncSetAttribute((const void*)avgmap_kernel,
                         cudaFuncAttributeMaxDynamicSharedMemorySize, SM_AVG);

    const size_t attn_elems = (size_t)NLAYER * BB * TT * TT;
    float* attn_out = out + ((size_t)out_size - attn_elems);

    {
        dim3 gw(WSEG_F / 4 / 256, 6);
        round_weights_kernel<<<gw, 256>>>(Wq, Wk, Wv, Wo, W1, W2, wp);
    }

    embed_kernel<<<(MT * CC + 255) / 256, 256>>>(x, emb, pos, xb);

    for (int l = 0; l < NLAYER; l++) {
        const float* wq = pWq + (size_t)l * CC * CC;
        const float* wk = pWk + (size_t)l * CC * CC;
        const float* wv = pWv + (size_t)l * CC * CC;
        const float* wo = pWo + (size_t)l * CC * CC;
        const float* w1 = pW1 + (size_t)l * FF * CC;
        const float* w2 = pW2 + (size_t)l * CC * FF;

        ln_kernel<1><<<MT / 8, 256>>>(xb, ln1g + (size_t)l * CC, ln1b + (size_t)l * CC, lnb);

        dim3 gqkv(CC / 128, MT / 128, 3);
        gemm_qkv_kernel<128, 128><<<gqkv, 256, SM_128_128>>>(
            lnb, wq, wk, wv,
            bq + (size_t)l * CC, bk + (size_t)l * CC, bv + (size_t)l * CC,
            qb, kb, vb);

        // fused flash attention: O + inv-l (main stream)
        dim3 gfl(TT / 128, NH, BB);
        flash_kernel<<<gfl, 256, SM_FLASH>>>(qb, kb, vb, ab);

        // fork: head-averaged attention map on side stream (grid halved)
        cudaEventRecord(g_si.evF[l], 0);
        cudaStreamWaitEvent(g_si.s2, g_si.evF[l], 0);
        dim3 gav(TT / 128, TT / 128, BB);
        avgmap_kernel<<<gav, 256, SM_AVG, g_si.s2>>>(
            qb, kb, attn_out + (size_t)l * BB * TT * TT);
        cudaEventRecord(g_si.evA[l], g_si.s2);

        // main stream continues: Wo projection + residual
        dim3 gwo(CC / 128, MT / 64, 1);
        gemm_tc_kernel<3, 64, 128><<<gwo, 256, SM_64_128>>>(
            ab, wo, bo + (size_t)l * CC, xb, xb, CC, CC, CC, CC);

        ln_kernel<1><<<MT / 8, 256>>>(xb, ln2g + (size_t)l * CC, ln2b + (size_t)l * CC, lnb);

        dim3 gf1(FF / 128, MT / 128, 1);
        gemm_tc_kernel<2, 128, 128><<<gf1, 256, SM_128_128>>>(
            lnb, w1, b1 + (size_t)l * FF, nullptr, fb, CC, CC, FF, CC);

        dim3 gf2(CC / 128, MT / 64, 1);
        gemm_tc_kernel<3, 64, 128><<<gf2, 256, SM_64_128>>>(
            fb, w2, b2 + (size_t)l * CC, xb, xb, FF, FF, CC, FF);

        // join: next layer's QKV overwrites q/k which avgmap reads
        cudaStreamWaitEvent(0, g_si.evA[l], 0);
    }

    ln_kernel<0><<<MT / 8, 256>>>(xb, lnfg, lnfb, lnb);
    final_mean_kernel<<<BB * CC, 256>>>(lnb, out);
}

// round 17
// speedup vs baseline: 1.0471x; 1.0086x over previous
#include <cuda_runtime.h>
#include <math.h>
#include <stdint.h>

#define NLAYER 4
#define BB 2
#define TT 2048
#define CC 512
#define NH 8
#define HDIM 64
#define FF 2048
#define VOCAB 32000
#define MT (BB*TT)   // 4096 rows

// ---------------- scratch (device globals; no allocations allowed) ----------
__device__ float g_x   [(size_t)MT*CC];
__device__ float g_ln  [(size_t)MT*CC];
__device__ float g_q   [(size_t)MT*CC];
__device__ float g_k   [(size_t)MT*CC];
__device__ float g_v   [(size_t)MT*CC];
__device__ float g_attn[(size_t)MT*CC];
__device__ float g_ff  [(size_t)MT*FF];
__device__ float g_linv[(size_t)BB*NH*TT];   // per-row 1/l from flash pass

// pre-rounded (tf32) weight copies: [Wq][Wk][Wv][Wo][W1][W2], each all-layers
#define WSEG_P (NLAYER*CC*CC)      // 1048576 (projection matrices)
#define WSEG_F (NLAYER*FF*CC)      // 4194304 (FFN matrices)
__device__ float g_wpack[(size_t)4*WSEG_P + 2*WSEG_F];   // ~50 MB

// ---------------- side stream + events (created at static init, reused) -----
struct StreamInit {
    cudaStream_t s2;
    cudaEvent_t evF[NLAYER], evA[NLAYER];
    StreamInit() {
        cudaStreamCreateWithFlags(&s2, cudaStreamNonBlocking);
        for (int i = 0; i < NLAYER; i++) {
            cudaEventCreateWithFlags(&evF[i], cudaEventDisableTiming);
            cudaEventCreateWithFlags(&evA[i], cudaEventDisableTiming);
        }
    }
};
static StreamInit g_si;

// ---------------- helpers ----------------------------------------------------
__device__ __forceinline__ uint32_t f2tf32(float x) {
    uint32_t u;
    asm("cvt.rna.tf32.f32 %0, %1;" : "=r"(u) : "f"(x));
    return u;
}
__device__ __forceinline__ float rnd_tf32(float x) {
    return __uint_as_float(f2tf32(x));
}

__device__ __forceinline__ float ex2(float x) {
    float y;
    asm("ex2.approx.f32 %0, %1;" : "=f"(y) : "f"(x));
    return y;
}

__device__ __forceinline__ void mma_tf32(float* c, const uint32_t* a, const uint32_t* b) {
    asm volatile(
        "mma.sync.aligned.m16n8k8.row.col.f32.tf32.tf32.f32 "
        "{%0,%1,%2,%3}, {%4,%5,%6,%7}, {%8,%9}, {%0,%1,%2,%3};"
        : "+f"(c[0]), "+f"(c[1]), "+f"(c[2]), "+f"(c[3])
        : "r"(a[0]), "r"(a[1]), "r"(a[2]), "r"(a[3]), "r"(b[0]), "r"(b[1]));
}

__device__ __forceinline__ void cp16(void* sdst, const void* gsrc) {
    unsigned s = (unsigned)__cvta_generic_to_shared(sdst);
    asm volatile("cp.async.cg.shared.global [%0], [%1], 16;\n" :: "r"(s), "l"(gsrc));
}
__device__ __forceinline__ void cp_commit() { asm volatile("cp.async.commit_group;\n"); }
template<int N>
__device__ __forceinline__ void cp_wait() { asm volatile("cp.async.wait_group %0;\n" :: "n"(N)); }

// ---------------- weight pre-rounding (runs once per launch) -----------------
__global__ void round_weights_kernel(const float* __restrict__ wq,
                                     const float* __restrict__ wk,
                                     const float* __restrict__ wv,
                                     const float* __restrict__ wo,
                                     const float* __restrict__ w1,
                                     const float* __restrict__ w2,
                                     float* __restrict__ dst) {
    const int seg = blockIdx.y;
    const float* src;
    size_t off, n;
    switch (seg) {
        case 0: src = wq; off = 0;                          n = WSEG_P; break;
        case 1: src = wk; off = (size_t)WSEG_P;             n = WSEG_P; break;
        case 2: src = wv; off = (size_t)2 * WSEG_P;         n = WSEG_P; break;
        case 3: src = wo; off = (size_t)3 * WSEG_P;         n = WSEG_P; break;
        case 4: src = w1; off = (size_t)4 * WSEG_P;         n = WSEG_F; break;
        default: src = w2; off = (size_t)4 * WSEG_P + WSEG_F; n = WSEG_F; break;
    }
    size_t i4 = (size_t)blockIdx.x * blockDim.x + threadIdx.x;
    if (i4 * 4 >= n) return;
    float4 t = ((const float4*)src)[i4];
    t.x = rnd_tf32(t.x); t.y = rnd_tf32(t.y);
    t.z = rnd_tf32(t.z); t.w = rnd_tf32(t.w);
    ((float4*)(dst + off))[i4] = t;
}

// =============================================================================
// TF32 tensor-core GEMM core (NT). C[M,N] = A[M,K] @ W[N,K]^T
// Pre-rounded operands; 3-stage cp.async pipeline, one sync per chunk.
// EPI: 1 = +bias, 2 = +bias,relu (tf32-rounded output), 3 = +bias,+residual
// =============================================================================
template<int EPI, int BM, int BN>
__device__ __forceinline__ void gemm_core(
    const float* __restrict__ A, const float* __restrict__ B,
    const float* __restrict__ bias, const float* __restrict__ res,
    float* __restrict__ C, int lda, int ldb, int ldc, int K)
{
    constexpr int WM   = BM / 64;
    constexpr int WN   = 8 / WM;
    constexpr int NCW  = BN / WN;
    constexpr int NT_  = NCW / 8;
    constexpr int ASZ  = BM * 36;
    constexpr int BSZ  = BN * 36;

    extern __shared__ float smem[];
    float* As = smem;                        // 3 * ASZ
    float* Bs = smem + 3 * ASZ;              // 3 * BSZ

    const int tid  = threadIdx.x;
    const int lane = tid & 31, wid = tid >> 5;
    const int warpM = (WM == 1) ? 0 : (wid & 1);
    const int warpN = (WM == 1) ? wid : (wid >> 1);
    const int grp = lane >> 2, qd = lane & 3;

    const int row0 = blockIdx.y * BM;
    const int col0 = blockIdx.x * BN;

    float acc[4][NT_][4];
#pragma unroll
    for (int mt = 0; mt < 4; mt++)
#pragma unroll
        for (int nt = 0; nt < NT_; nt++)
#pragma unroll
            for (int i = 0; i < 4; i++) acc[mt][nt][i] = 0.f;

    auto loadA = [&](int buf, int k0) {
#pragma unroll
        for (int i = 0; i < BM / 32; i++) {
            int idx = i * 256 + tid;
            int r = idx >> 3, c4 = (idx & 7) << 2;
            cp16(As + buf * ASZ + r * 36 + c4,
                 A + (size_t)(row0 + r) * lda + k0 + c4);
        }
    };
    auto loadB = [&](int buf, int k0) {
#pragma unroll
        for (int i = 0; i < BN / 32; i++) {
            int idx = i * 256 + tid;
            int r = idx >> 3, c4 = (idx & 7) << 2;
            cp16(Bs + buf * BSZ + r * 36 + c4,
                 B + (size_t)(col0 + r) * ldb + k0 + c4);
        }
    };

    auto compute = [&](int buf) {
        const float* Ab = As + buf * ASZ;
        const float* Bb = Bs + buf * BSZ;
#pragma unroll
        for (int kt = 0; kt < 4; kt++) {
            uint32_t af[4][4];
#pragma unroll
            for (int mt = 0; mt < 4; mt++) {
                int r0 = warpM * 64 + mt * 16 + grp;
                af[mt][0] = __float_as_uint(Ab[(r0)     * 36 + kt * 8 + qd]);
                af[mt][1] = __float_as_uint(Ab[(r0 + 8) * 36 + kt * 8 + qd]);
                af[mt][2] = __float_as_uint(Ab[(r0)     * 36 + kt * 8 + qd + 4]);
                af[mt][3] = __float_as_uint(Ab[(r0 + 8) * 36 + kt * 8 + qd + 4]);
            }
            uint32_t bf[NT_][2];
#pragma unroll
            for (int nt = 0; nt < NT_; nt++) {
                int nb = warpN * NCW + nt * 8 + grp;
                bf[nt][0] = __float_as_uint(Bb[nb * 36 + kt * 8 + qd]);
                bf[nt][1] = __float_as_uint(Bb[nb * 36 + kt * 8 + qd + 4]);
            }
#pragma unroll
            for (int mt = 0; mt < 4; mt++)
#pragma unroll
                for (int nt = 0; nt < NT_; nt++)
                    mma_tf32(acc[mt][nt], af[mt], bf[nt]);
        }
    };

    const int nk = K >> 5;
    loadA(0, 0);  loadB(0, 0);  cp_commit();
    loadA(1, 32); loadB(1, 32); cp_commit();

    int buf = 0;
    int nbuf = 2;
    for (int kb = 0; kb < nk; kb++) {
        cp_wait<1>();
        __syncthreads();
        int nb = kb + 2;
        if (nb < nk) { loadA(nbuf, nb * 32); loadB(nbuf, nb * 32); }
        cp_commit();
        compute(buf);
        buf = (buf == 2) ? 0 : buf + 1;
        nbuf = (nbuf == 2) ? 0 : nbuf + 1;
    }

#pragma unroll
    for (int mt = 0; mt < 4; mt++)
#pragma unroll
        for (int nt = 0; nt < NT_; nt++) {
            int row = row0 + warpM * 64 + mt * 16 + grp;
            int col = col0 + warpN * NCW + nt * 8 + qd * 2;
#pragma unroll
            for (int half = 0; half < 2; half++) {
                int r = row + half * 8;
                float v0 = acc[mt][nt][half * 2 + 0];
                float v1 = acc[mt][nt][half * 2 + 1];
                v0 += bias[col]; v1 += bias[col + 1];
                if (EPI == 2) {
                    v0 = rnd_tf32(fmaxf(v0, 0.f));
                    v1 = rnd_tf32(fmaxf(v1, 0.f));
                }
                if (EPI == 3) {
                    v0 += res[(size_t)r * ldc + col];
                    v1 += res[(size_t)r * ldc + col + 1];
                }
                *(float2*)(C + (size_t)r * ldc + col) = make_float2(v0, v1);
            }
        }
}

template<int EPI, int BM, int BN>
__global__ void __launch_bounds__(256, 2)
gemm_tc_kernel(const float* __restrict__ A, const float* __restrict__ B,
               const float* __restrict__ bias, const float* __restrict__ res,
               float* __restrict__ C, int lda, int ldb, int ldc, int K) {
    gemm_core<EPI, BM, BN>(A, B, bias, res, C, lda, ldb, ldc, K);
}

// ---- fused QKV (z selects weight/bias/output); BN=128 (validated) -----------
template<int BM, int BN>
__global__ void __launch_bounds__(256, 2)
gemm_qkv_kernel(const float* __restrict__ A,
                const float* __restrict__ Wq, const float* __restrict__ Wk,
                const float* __restrict__ Wv,
                const float* __restrict__ bq, const float* __restrict__ bk,
                const float* __restrict__ bv,
                float* __restrict__ q, float* __restrict__ k, float* __restrict__ v) {
    int z = blockIdx.z;
    const float* B    = z == 0 ? Wq : (z == 1 ? Wk : Wv);
    const float* bias = z == 0 ? bq : (z == 1 ? bk : bv);
    float* C          = z == 0 ? q  : (z == 1 ? k  : v);
    gemm_core<1, BM, BN>(A, B, bias, nullptr, C, CC, CC, CC, CC);
}

// =============================================================================
// Flash attention pass 1: max-free softmax, transposed V, NO cvt in staging
// (mma.tf32 truncates raw fp32 bits; flash and avgmap truncate consistently),
// DEFERRED l reduction (per-lane partials, one shuffle after the loop).
// =============================================================================
__global__ void __launch_bounds__(256, 2)
flash_kernel(const float* __restrict__ q, const float* __restrict__ k,
             const float* __restrict__ v, float* __restrict__ o) {
    constexpr int KT = 32, NKT = TT / KT;
    constexpr int KBLK = 68;
    constexpr int PVT = 56;
    const float SCALEQ = 0.125f * 1.44269504089f;
    extern __shared__ uint32_t usm[];
    uint32_t* Kf = usm;                     // 2 * 32 * 68
    uint32_t* Vt = usm + 2 * 32 * KBLK;     // 2 * 64 * 56

    const int qt = blockIdx.x, h = blockIdx.y, b = blockIdx.z;
    const int tid = threadIdx.x, lane = tid & 31, w = tid >> 5;
    const int grp = lane >> 2, qd = lane & 3;
    const int rbase = w * 16;

    const float* Qp = q + ((size_t)(b * TT) + qt * 128) * CC + h * 64;
    const float* Kp = k + (size_t)b * TT * CC + h * 64;
    const float* Vp = v + (size_t)b * TT * CC + h * 64;

    uint32_t qf[8][4];
#pragma unroll
    for (int k8 = 0; k8 < 8; k8++) {
        const float* Qr0 = Qp + (size_t)(rbase + grp) * CC + k8 * 8 + qd;
        const float* Qr1 = Qr0 + (size_t)8 * CC;
        qf[k8][0] = __float_as_uint(Qr0[0] * SCALEQ);
        qf[k8][1] = __float_as_uint(Qr1[0] * SCALEQ);
        qf[k8][2] = __float_as_uint(Qr0[4] * SCALEQ);
        qf[k8][3] = __float_as_uint(Qr1[4] * SCALEQ);
    }

    const int skr = tid >> 3, skc = (tid & 7) * 8;
    const int vc = tid & 63, vrb = (tid >> 6) * 8;

    float4 kr0, kr1;
    float vreg[8];
    auto ldgKV = [&](int kt) {
        const float* Kt = Kp + (size_t)(kt * KT + skr) * CC + skc;
        kr0 = *(const float4*)(Kt);
        kr1 = *(const float4*)(Kt + 4);
        const float* Vtg = Vp + (size_t)(kt * KT + vrb) * CC + vc;
#pragma unroll
        for (int i = 0; i < 8; i++) vreg[i] = Vtg[(size_t)i * CC];
    };
    auto stsKV = [&](int buf) {
        uint32_t* kd = Kf + buf * 32 * KBLK
                     + ((skr >> 3) * 8 + (skc >> 3)) * KBLK + (skr & 7) * 8;
        uint4 ua, ub;
        ua.x = __float_as_uint(kr0.x); ua.y = __float_as_uint(kr1.x);
        ua.z = __float_as_uint(kr0.y); ua.w = __float_as_uint(kr1.y);
        ub.x = __float_as_uint(kr0.z); ub.y = __float_as_uint(kr1.z);
        ub.z = __float_as_uint(kr0.w); ub.w = __float_as_uint(kr1.w);
        *(uint4*)(kd)     = ua;
        *(uint4*)(kd + 4) = ub;
        uint32_t* vd = Vt + buf * 64 * PVT + vc * PVT + vrb;
        uint4 u0, u1;
        u0.x = __float_as_uint(vreg[0]); u0.y = __float_as_uint(vreg[1]);
        u0.z = __float_as_uint(vreg[2]); u0.w = __float_as_uint(vreg[3]);
        u1.x = __float_as_uint(vreg[4]); u1.y = __float_as_uint(vreg[5]);
        u1.z = __float_as_uint(vreg[6]); u1.w = __float_as_uint(vreg[7]);
        *(uint4*)(vd)     = u0;
        *(uint4*)(vd + 4) = u1;
    };

    float oacc[8][4];
#pragma unroll
    for (int nt = 0; nt < 8; nt++)
#pragma unroll
        for (int i = 0; i < 4; i++) oacc[nt][i] = 0.f;
    float l0 = 0.f, l1 = 0.f;   // per-lane partials; reduced after the loop

    ldgKV(0);
    stsKV(0);
    __syncthreads();

    for (int kt = 0; kt < NKT; kt++) {
        const int buf = kt & 1;
        if (kt + 1 < NKT) ldgKV(kt + 1);

        const uint32_t* Kb = Kf + buf * 32 * KBLK;
        const uint32_t* Vb = Vt + buf * 64 * PVT;

        float sacc[4][4];
#pragma unroll
        for (int nt = 0; nt < 4; nt++)
#pragma unroll
            for (int i = 0; i < 4; i++) sacc[nt][i] = 0.f;
#pragma unroll
        for (int k8 = 0; k8 < 8; k8++) {
#pragma unroll
            for (int nt = 0; nt < 4; nt++) {
                uint2 p = *(const uint2*)(Kb + (nt * 8 + k8) * KBLK + grp * 8 + qd * 2);
                uint32_t bf[2] = {p.x, p.y};
                mma_tf32(sacc[nt], qf[k8], bf);
            }
        }

        // p = 2^s; accumulate per-lane partial row sums (no shuffles in loop)
#pragma unroll
        for (int nt = 0; nt < 4; nt++) {
            sacc[nt][0] = ex2(sacc[nt][0]);
            sacc[nt][1] = ex2(sacc[nt][1]);
            sacc[nt][2] = ex2(sacc[nt][2]);
            sacc[nt][3] = ex2(sacc[nt][3]);
            l0 += sacc[nt][0] + sacc[nt][1];
            l1 += sacc[nt][2] + sacc[nt][3];
        }

        // O += P @ V : S accumulator fed directly (raw bits -> HW truncation)
#pragma unroll
        for (int kb = 0; kb < 4; kb++) {
            uint32_t af[4];
            af[0] = __float_as_uint(sacc[kb][0]);
            af[1] = __float_as_uint(sacc[kb][2]);
            af[2] = __float_as_uint(sacc[kb][1]);
            af[3] = __float_as_uint(sacc[kb][3]);
#pragma unroll
            for (int nt = 0; nt < 8; nt++) {
                uint2 p = *(const uint2*)(Vb + (nt * 8 + grp) * PVT + kb * 8 + 2 * qd);
                uint32_t bf[2] = {p.x, p.y};
                mma_tf32(oacc[nt], af, bf);
            }
        }

        if (kt + 1 < NKT) stsKV(buf ^ 1);
        __syncthreads();
    }

    // deferred row-sum reduction (over the 4 quad lanes)
    l0 += __shfl_xor_sync(0xffffffffu, l0, 1);
    l0 += __shfl_xor_sync(0xffffffffu, l0, 2);
    l1 += __shfl_xor_sync(0xffffffffu, l1, 1);
    l1 += __shfl_xor_sync(0xffffffffu, l1, 2);

    float i0 = 1.f / l0, i1 = 1.f / l1;
    int row0 = qt * 128 + rbase + grp;
    float* Op = o + ((size_t)(b * TT) + row0) * CC + h * 64;
#pragma unroll
    for (int nt = 0; nt < 8; nt++) {
        *(float2*)(Op + nt * 8 + qd * 2) =
            make_float2(rnd_tf32(oacc[nt][0] * i0), rnd_tf32(oacc[nt][1] * i0));
        *(float2*)(Op + (size_t)8 * CC + nt * 8 + qd * 2) =
            make_float2(rnd_tf32(oacc[nt][2] * i1), rnd_tf32(oacc[nt][3] * i1));
    }
    if (qd == 0) {
        g_linv[(size_t)(b * NH + h) * TT + row0]     = i0;
        g_linv[(size_t)(b * NH + h) * TT + row0 + 8] = i1;
    }
}

// =============================================================================
// Pass 2: head-averaged attention map, 2 kc-chunks per CTA, NO cvt in staging
// (raw bits -> HW truncation, consistent with flash).
// =============================================================================
__global__ void __launch_bounds__(256, 2)
avgmap_kernel(const float* __restrict__ q, const float* __restrict__ k,
              float* __restrict__ avg) {
    constexpr int QBLK = 132, KBLK = 68;
    const float C2 = 0.125f * 1.44269504089f;
    extern __shared__ uint32_t usm[];
    uint32_t* QF = usm;
    uint32_t* KF = usm + 64 * QBLK;
    float* St = (float*)(usm + 64 * QBLK + 64 * KBLK);   // [8][128] inv-l

    const int kc2 = blockIdx.x, qt = blockIdx.y, b = blockIdx.z;
    const int tid = threadIdx.x, lane = tid & 31, w = tid >> 5;
    const int grp = lane >> 2, qd = lane & 3;
    const int wm = w >> 1, wn = w & 1;

    for (int j = tid; j < NH * 128; j += 256)
        St[j] = g_linv[(size_t)(b * NH + (j >> 7)) * TT + qt * 128 + (j & 127)];

    const int kkr = tid >> 2, kc0 = (tid & 3) * 16;
    float4 kreg[4];

    for (int kcc = 0; kcc < 2; kcc++) {
        const int kc = kc2 * 2 + kcc;

        auto ldgK = [&](int h) {
            const float* Kp = k + ((size_t)(b * TT) + kc * 64 + kkr) * CC + h * 64 + kc0;
#pragma unroll
            for (int i = 0; i < 4; i++) kreg[i] = *(const float4*)(Kp + i * 4);
        };

        float aacc[2][4][4];
#pragma unroll
        for (int mt = 0; mt < 2; mt++)
#pragma unroll
            for (int nt = 0; nt < 4; nt++)
#pragma unroll
                for (int i = 0; i < 4; i++) aacc[mt][nt][i] = 0.f;

        ldgK(0);

        for (int h = 0; h < NH; h++) {
            __syncthreads();
            {
                uint32_t* kb0 = KF + ((kkr >> 3) * 8 + (kc0 >> 3)) * KBLK + (kkr & 7) * 8;
#pragma unroll
                for (int bb = 0; bb < 2; bb++) {
                    float4 f0 = kreg[bb * 2], f1 = kreg[bb * 2 + 1];
                    uint4 ua, ub;
                    ua.x = __float_as_uint(f0.x); ua.y = __float_as_uint(f1.x);
                    ua.z = __float_as_uint(f0.y); ua.w = __float_as_uint(f1.y);
                    ub.x = __float_as_uint(f0.z); ub.y = __float_as_uint(f1.z);
                    ub.z = __float_as_uint(f0.w); ub.w = __float_as_uint(f1.w);
                    *(uint4*)(kb0 + bb * KBLK)     = ua;
                    *(uint4*)(kb0 + bb * KBLK + 4) = ub;
                }
            }
            {
                const float* Qp = q + ((size_t)(b * TT) + qt * 128) * CC + h * 64;
#pragma unroll
                for (int i = 0; i < 8; i++) {
                    int j = i * 256 + tid;
                    int r = j >> 4, c4 = (j & 15) << 2;
                    float4 t4 = *(const float4*)(Qp + (size_t)r * CC + c4);
                    int blk  = (r >> 4) * 8 + (c4 >> 3);
                    int base = blk * QBLK + ((c4 >> 2) & 1) * 2 + ((r >> 3) & 1);
                    int ro   = (r & 7) * 4;
                    QF[base + (ro + 0) * 4] = __float_as_uint(t4.x);
                    QF[base + (ro + 1) * 4] = __float_as_uint(t4.y);
                    QF[base + (ro + 2) * 4] = __float_as_uint(t4.z);
                    QF[base + (ro + 3) * 4] = __float_as_uint(t4.w);
                }
            }
            if (h + 1 < NH) ldgK(h + 1);
            __syncthreads();

            float sacc[2][4][4];
#pragma unroll
            for (int mt = 0; mt < 2; mt++)
#pragma unroll
                for (int nt = 0; nt < 4; nt++)
#pragma unroll
                    for (int i = 0; i < 4; i++) sacc[mt][nt][i] = 0.f;

#pragma unroll
            for (int k8 = 0; k8 < 8; k8++) {
                uint32_t af[2][4];
#pragma unroll
                for (int mt = 0; mt < 2; mt++) {
                    uint4 u = *(const uint4*)(QF + ((wm * 2 + mt) * 8 + k8) * QBLK
                                              + (grp * 4 + qd) * 4);
                    af[mt][0] = u.x; af[mt][1] = u.y; af[mt][2] = u.z; af[mt][3] = u.w;
                }
#pragma unroll
                for (int nt = 0; nt < 4; nt++) {
                    uint2 p = *(const uint2*)(KF + ((wn * 4 + nt) * 8 + k8) * KBLK
                                              + grp * 8 + qd * 2);
                    uint32_t bf[2] = {p.x, p.y};
                    mma_tf32(sacc[0][nt], af[0], bf);
                    mma_tf32(sacc[1][nt], af[1], bf);
                }
            }

#pragma unroll
            for (int mt = 0; mt < 2; mt++) {
                int r0 = wm * 32 + mt * 16 + grp;
                float il0 = St[h * 128 + r0];
                float il1 = St[h * 128 + r0 + 8];
#pragma unroll
                for (int nt = 0; nt < 4; nt++) {
                    aacc[mt][nt][0] += ex2(sacc[mt][nt][0] * C2) * il0;
                    aacc[mt][nt][1] += ex2(sacc[mt][nt][1] * C2) * il0;
                    aacc[mt][nt][2] += ex2(sacc[mt][nt][2] * C2) * il1;
                    aacc[mt][nt][3] += ex2(sacc[mt][nt][3] * C2) * il1;
                }
            }
        }

        const float inv8 = 1.0f / NH;
#pragma unroll
        for (int mt = 0; mt < 2; mt++) {
            int qrow = qt * 128 + wm * 32 + mt * 16 + grp;
            int kcol = kc * 64 + wn * 32;
            float* A0 = avg + ((size_t)(b * TT) + qrow) * TT + kcol;
            float* A1 = A0 + (size_t)8 * TT;
#pragma unroll
            for (int nt = 0; nt < 4; nt++) {
                *(float2*)(A0 + nt * 8 + qd * 2) =
                    make_float2(aacc[mt][nt][0] * inv8, aacc[mt][nt][1] * inv8);
                *(float2*)(A1 + nt * 8 + qd * 2) =
                    make_float2(aacc[mt][nt][2] * inv8, aacc[mt][nt][3] * inv8);
            }
        }
    }
}

// ---------------- embedding + positional ------------------------------------
__global__ void embed_kernel(const int* __restrict__ x,
                             const float* __restrict__ emb,
                             const float* __restrict__ pos,
                             float* __restrict__ out) {
    int idx = blockIdx.x * blockDim.x + threadIdx.x;
    if (idx >= MT * CC) return;
    int c  = idx % CC;
    int bt = idx / CC;
    int t  = bt % TT;
    int tok = x[bt];
    if (tok < 0) tok = 0;
    if (tok >= VOCAB) tok = VOCAB - 1;
    out[idx] = emb[(size_t)tok * CC + c] + pos[(size_t)t * CC + c];
}

// ---------------- layernorm: one warp per 512-float row ----------------------
template<int RND>
__global__ void ln_kernel(const float* __restrict__ in,
                          const float* __restrict__ g,
                          const float* __restrict__ b,
                          float* __restrict__ out) {
    int row  = blockIdx.x * 8 + (threadIdx.x >> 5);
    int lane = threadIdx.x & 31;
    const float4* xr = (const float4*)(in + (size_t)row * CC);
    float4 v[4];
    float s = 0.f;
#pragma unroll
    for (int i = 0; i < 4; i++) {
        v[i] = xr[i * 32 + lane];
        s += v[i].x + v[i].y + v[i].z + v[i].w;
    }
#pragma unroll
    for (int o = 16; o; o >>= 1) s += __shfl_xor_sync(0xffffffffu, s, o);
    float mean = s * (1.0f / CC);
    float var = 0.f;
#pragma unroll
    for (int i = 0; i < 4; i++) {
        float dx = v[i].x - mean, dy = v[i].y - mean, dz = v[i].z - mean, dw = v[i].w - mean;
        var += dx * dx + dy * dy + dz * dz + dw * dw;
    }
#pragma unroll
    for (int o = 16; o; o >>= 1) var += __shfl_xor_sync(0xffffffffu, var, o);
    float rstd = rsqrtf(var * (1.0f / CC) + 1e-5f);
    float4* op = (float4*)(out + (size_t)row * CC);
    const float4* gp = (const float4*)g;
    const float4* bp = (const float4*)b;
#pragma unroll
    for (int i = 0; i < 4; i++) {
        float4 gg = gp[i * 32 + lane], bb = bp[i * 32 + lane];
        float4 o4;
        o4.x = (v[i].x - mean) * rstd * gg.x + bb.x;
        o4.y = (v[i].y - mean) * rstd * gg.y + bb.y;
        o4.z = (v[i].z - mean) * rstd * gg.z + bb.z;
        o4.w = (v[i].w - mean) * rstd * gg.w + bb.w;
        if (RND) {
            o4.x = rnd_tf32(o4.x); o4.y = rnd_tf32(o4.y);
            o4.z = rnd_tf32(o4.z); o4.w = rnd_tf32(o4.w);
        }
        op[i * 32 + lane] = o4;
    }
}

// ---------------- final pooled output: mean over T of lnf(x) ----------------
__global__ void final_mean_kernel(const float* __restrict__ hln,
                                  float* __restrict__ out) {
    int bd = blockIdx.x;
    int b = bd / CC, d = bd % CC;
    __shared__ float red[256];
    int tid = threadIdx.x;
    float s = 0.f;
    for (int t = tid; t < TT; t += 256)
        s += hln[((size_t)b * TT + t) * CC + d];
    red[tid] = s; __syncthreads();
    for (int o = 128; o > 0; o >>= 1) { if (tid < o) red[tid] += red[tid + o]; __syncthreads(); }
    if (tid == 0) out[bd] = red[0] * (1.0f / TT);
}

// ---------------- launch ------------------------------------------------------
extern "C" void kernel_launch(void* const* d_in, const int* in_sizes, int n_in,
                              void* d_out, int out_size) {
    const int* x      = (const int*)d_in[0];
    const float* emb  = (const float*)d_in[1];
    const float* pos  = (const float*)d_in[2];
    const float* Wq = (const float*)d_in[3],  *bq = (const float*)d_in[4];
    const float* Wk = (const float*)d_in[5],  *bk = (const float*)d_in[6];
    const float* Wv = (const float*)d_in[7],  *bv = (const float*)d_in[8];
    const float* Wo = (const float*)d_in[9],  *bo = (const float*)d_in[10];
    const float* W1 = (const float*)d_in[11], *b1 = (const float*)d_in[12];
    const float* W2 = (const float*)d_in[13], *b2 = (const float*)d_in[14];
    const float* ln1g = (const float*)d_in[15], *ln1b = (const float*)d_in[16];
    const float* ln2g = (const float*)d_in[17], *ln2b = (const float*)d_in[18];
    const float* lnfg = (const float*)d_in[19], *lnfb = (const float*)d_in[20];
    float* out = (float*)d_out;

    float *xb, *lnb, *qb, *kb, *vb, *ab, *fb, *wp;
    cudaGetSymbolAddress((void**)&xb,  g_x);
    cudaGetSymbolAddress((void**)&lnb, g_ln);
    cudaGetSymbolAddress((void**)&qb,  g_q);
    cudaGetSymbolAddress((void**)&kb,  g_k);
    cudaGetSymbolAddress((void**)&vb,  g_v);
    cudaGetSymbolAddress((void**)&ab,  g_attn);
    cudaGetSymbolAddress((void**)&fb,  g_ff);
    cudaGetSymbolAddress((void**)&wp,  g_wpack);

    const float* pWq = wp;
    const float* pWk = wp + (size_t)WSEG_P;
    const float* pWv = wp + (size_t)2 * WSEG_P;
    const float* pWo = wp + (size_t)3 * WSEG_P;
    const float* pW1 = wp + (size_t)4 * WSEG_P;
    const float* pW2 = wp + (size_t)4 * WSEG_P + WSEG_F;

    const int SM_128_128 = 3 * (128 * 36 + 128 * 36) * 4;               // 110592
    const int SM_64_128  = 3 * (64 * 36 + 128 * 36) * 4;                // 82944
    const int SM_FLASH   = (2 * 32 * 68 + 2 * 64 * 56) * 4;             // 46080
    const int SM_AVG     = (64 * 132 + 64 * 68) * 4 + NH * 128 * 4;     // 55296

    cudaFuncSetAttribute((const void*)gemm_qkv_kernel<128, 128>,
                         cudaFuncAttributeMaxDynamicSharedMemorySize, SM_128_128);
    cudaFuncSetAttribute((const void*)gemm_tc_kernel<2, 128, 128>,
                         cudaFuncAttributeMaxDynamicSharedMemorySize, SM_128_128);
    cudaFuncSetAttribute((const void*)gemm_tc_kernel<3, 64, 128>,
                         cudaFuncAttributeMaxDynamicSharedMemorySize, SM_64_128);
    cudaFuncSetAttribute((const void*)flash_kernel,
                         cudaFuncAttributeMaxDynamicSharedMemorySize, SM_FLASH);
    cudaFuncSetAttribute((const void*)avgmap_kernel,
                         cudaFuncAttributeMaxDynamicSharedMemorySize, SM_AVG);

    const size_t attn_elems = (size_t)NLAYER * BB * TT * TT;
    float* attn_out = out + ((size_t)out_size - attn_elems);

    {
        dim3 gw(WSEG_F / 4 / 256, 6);
        round_weights_kernel<<<gw, 256>>>(Wq, Wk, Wv, Wo, W1, W2, wp);
    }

    embed_kernel<<<(MT * CC + 255) / 256, 256>>>(x, emb, pos, xb);

    for (int l = 0; l < NLAYER; l++) {
        const float* wq = pWq + (size_t)l * CC * CC;
        const float* wk = pWk + (size_t)l * CC * CC;
        const float* wv = pWv + (size_t)l * CC * CC;
        const float* wo = pWo + (size_t)l * CC * CC;
        const float* w1 = pW1 + (size_t)l * FF * CC;
        const float* w2 = pW2 + (size_t)l * CC * FF;

        ln_kernel<1><<<MT / 8, 256>>>(xb, ln1g + (size_t)l * CC, ln1b + (size_t)l * CC, lnb);

        dim3 gqkv(CC / 128, MT / 128, 3);
        gemm_qkv_kernel<128, 128><<<gqkv, 256, SM_128_128>>>(
            lnb, wq, wk, wv,
            bq + (size_t)l * CC, bk + (size_t)l * CC, bv + (size_t)l * CC,
            qb, kb, vb);

        // fused flash attention: O + inv-l (main stream)
        dim3 gfl(TT / 128, NH, BB);
        flash_kernel<<<gfl, 256, SM_FLASH>>>(qb, kb, vb, ab);

        // fork: head-averaged attention map on side stream
        cudaEventRecord(g_si.evF[l], 0);
        cudaStreamWaitEvent(g_si.s2, g_si.evF[l], 0);
        dim3 gav(TT / 128, TT / 128, BB);
        avgmap_kernel<<<gav, 256, SM_AVG, g_si.s2>>>(
            qb, kb, attn_out + (size_t)l * BB * TT * TT);
        cudaEventRecord(g_si.evA[l], g_si.s2);

        // main stream continues: Wo projection + residual
        dim3 gwo(CC / 128, MT / 64, 1);
        gemm_tc_kernel<3, 64, 128><<<gwo, 256, SM_64_128>>>(
            ab, wo, bo + (size_t)l * CC, xb, xb, CC, CC, CC, CC);

        ln_kernel<1><<<MT / 8, 256>>>(xb, ln2g + (size_t)l * CC, ln2b + (size_t)l * CC, lnb);

        dim3 gf1(FF / 128, MT / 128, 1);
        gemm_tc_kernel<2, 128, 128><<<gf1, 256, SM_128_128>>>(
            lnb, w1, b1 + (size_t)l * FF, nullptr, fb, CC, CC, FF, CC);

        dim3 gf2(CC / 128, MT / 64, 1);
        gemm_tc_kernel<3, 64, 128><<<gf2, 256, SM_64_128>>>(
            fb, w2, b2 + (size_t)l * CC, xb, xb, FF, FF, CC, FF);

        // join: next layer's QKV overwrites q/k which avgmap reads
        cudaStreamWaitEvent(0, g_si.evA[l], 0);
    }

    ln_kernel<0><<<MT / 8, 256>>>(xb, lnfg, lnfb, lnb);
    final_mean_kernel<<<BB * CC, 256>>>(lnb, out);
}